// round 11
// baseline (speedup 1.0000x reference)
#include <cuda_runtime.h>
#include <cstddef>
#include <cstdint>

#define B_  32
#define N_  4096
#define DIN 256
#define D_  256
#define S_  16
#define H_  512
#define EPS 1e-5f
#define SCALE 0.0625f
#define NGRP 8               // groups per batch (512 n per group)
#define SUBS 16              // subtiles per group
#define RSUB 32              // rows per subtile
#define XS 260               // xsm row stride (floats)
#define AS 20                // atsm row stride
#define ROWS (B_*S_)         // 512

typedef unsigned long long u64;

__device__ __forceinline__ u64 fma2(u64 a, u64 b, u64 c) {
    u64 d;
    asm("fma.rn.f32x2 %0, %1, %2, %3;" : "=l"(d) : "l"(a), "l"(b), "l"(c));
    return d;
}
__device__ __forceinline__ u64 pack2(float lo, float hi) {
    u64 d;
    asm("mov.b64 %0, {%1, %2};" : "=l"(d) : "f"(lo), "f"(hi));
    return d;
}
__device__ __forceinline__ void unpack2(u64 v, float& lo, float& hi) {
    asm("mov.b64 {%0, %1}, %2;" : "=f"(lo), "=f"(hi) : "l"(v));
}
__device__ __forceinline__ float hsum2(u64 v) {
    float a, b; unpack2(v, a, b); return a + b;
}
__device__ __forceinline__ float sigmoidf(float x) { return 1.0f / (1.0f + __expf(-x)); }

__device__ __forceinline__ void cp_async16(uint32_t dst, const float* src) {
    asm volatile("cp.async.ca.shared.global [%0], [%1], 16;" :: "r"(dst), "l"(src));
}
__device__ __forceinline__ void cp_commit() {
    asm volatile("cp.async.commit_group;");
}
__device__ __forceinline__ void cp_wait1() {
    asm volatile("cp.async.wait_group 1;" ::: "memory");
}

// ---------------- scratch ----------------
__device__ float g_xln [(size_t)B_ * N_ * DIN];
__device__ float g_slots[ROWS * D_];
__device__ float g_qk   [ROWS * DIN];
__device__ float g_ct   [ROWS];
__device__ float g_uv   [ROWS * DIN];
__device__ float g_r    [ROWS];
__device__ float g_part [(size_t)B_ * NGRP * S_ * DIN];
__device__ float g_rpart[B_ * NGRP * S_];
__device__ float g_gi   [ROWS * 3 * D_];
__device__ float g_gh   [ROWS * 3 * D_];
__device__ float g_h    [ROWS * D_];
__device__ float g_m    [ROWS * D_];
__device__ float g_t    [ROWS * H_];
__device__ float g_Wqk  [DIN * D_];
__device__ float g_Wiv  [3 * D_ * DIN];
__device__ float g_us   [D_];
__device__ float g_bqk  [DIN];
__device__ float g_biv  [3 * D_];
__device__ float g_c0   [1];
__device__ float g_prec [4 * 64 * 4096];

// ---------------- slots init ----------------
__global__ void slots_init_kernel(const float* __restrict__ noise,
                                  const float* __restrict__ mu,
                                  const float* __restrict__ sigma,
                                  float* __restrict__ slots) {
    int i = blockIdx.x * 256 + threadIdx.x;
    int d = i & (D_ - 1);
    slots[i] = mu[d] + sigma[d] * noise[i];
}

// ---------------- LayerNorm (inputs), warp per 256-row ----------------
__global__ void ln_rows_kernel(const float* __restrict__ X,
                               const float* __restrict__ gg,
                               const float* __restrict__ bb,
                               float* __restrict__ Y, int rows) {
    int warp = threadIdx.x >> 5, lane = threadIdx.x & 31;
    int row = blockIdx.x * 8 + warp;
    if (row >= rows) return;
    const float4* x4 = (const float4*)(X + (size_t)row * 256);
    float4 a = x4[lane];
    float4 c = x4[lane + 32];
    float s  = a.x + a.y + a.z + a.w + c.x + c.y + c.z + c.w;
    float s2 = a.x*a.x + a.y*a.y + a.z*a.z + a.w*a.w
             + c.x*c.x + c.y*c.y + c.z*c.z + c.w*c.w;
    #pragma unroll
    for (int o = 16; o; o >>= 1) {
        s  += __shfl_xor_sync(0xffffffffu, s,  o);
        s2 += __shfl_xor_sync(0xffffffffu, s2, o);
    }
    float mean = s * (1.0f / 256.0f);
    float var  = s2 * (1.0f / 256.0f) - mean * mean;
    float rstd = rsqrtf(var + EPS);
    const float4* g4 = (const float4*)gg;
    const float4* b4 = (const float4*)bb;
    float4 ga = g4[lane], gc = g4[lane + 32];
    float4 ba = b4[lane], bc = b4[lane + 32];
    float4 o1, o2;
    o1.x = (a.x - mean) * rstd * ga.x + ba.x;
    o1.y = (a.y - mean) * rstd * ga.y + ba.y;
    o1.z = (a.z - mean) * rstd * ga.z + ba.z;
    o1.w = (a.w - mean) * rstd * ga.w + ba.w;
    o2.x = (c.x - mean) * rstd * gc.x + bc.x;
    o2.y = (c.y - mean) * rstd * gc.y + bc.y;
    o2.z = (c.z - mean) * rstd * gc.z + bc.z;
    o2.w = (c.w - mean) * rstd * gc.w + bc.w;
    float4* y4 = (float4*)(Y + (size_t)row * 256);
    y4[lane] = o1;
    y4[lane + 32] = o2;
}

// ------------- combined split-k precompute + prep -------------------------
__global__ __launch_bounds__(256) void prec_kernel(
    const float* __restrict__ Wk, const float* __restrict__ Wq,
    const float* __restrict__ Wih, const float* __restrict__ Wv,
    const float* __restrict__ bk, const float* __restrict__ bq,
    const float* __restrict__ bv,
    float* __restrict__ partial,
    float* __restrict__ us, float* __restrict__ bqk,
    float* __restrict__ c0, float* __restrict__ biv) {
    int t = threadIdx.x;
    int tile = blockIdx.x, ks = blockIdx.y;

    if (tile >= 64) {
        if (ks != 0) return;
        int bx = tile - 64;
        if (bx < 96) {
            int warp = t >> 5, lane = t & 31;
            int r = bx * 8 + warp;
            float s = 0.0f;
            #pragma unroll
            for (int e = lane; e < D_; e += 32) s += Wih[(size_t)r * D_ + e] * bv[e];
            #pragma unroll
            for (int o = 16; o; o >>= 1) s += __shfl_xor_sync(0xffffffffu, s, o);
            if (lane == 0) biv[r] = s;
        } else if (bx == 96) {
            float s = 0.0f;
            for (int e = 0; e < D_; e++) s += bk[e] * Wq[(size_t)e * D_ + t];
            us[t] = SCALE * s;
            if (t == 0) {
                float c = 0.0f;
                for (int e = 0; e < D_; e++) c += bk[e] * bq[e];
                *c0 = SCALE * c;
            }
        } else {
            float s = 0.0f;
            for (int e = 0; e < D_; e++) s += bq[e] * Wk[(size_t)e * DIN + t];
            bqk[t] = SCALE * s;
        }
        return;
    }

    __shared__ float As[16][68];
    __shared__ float Bs[16][68];
    bool ta = (tile < 16);
    int t2 = ta ? tile : tile - 16;
    int m0 = (t2 >> 2) * 64, n0 = (t2 & 3) * 64;
    const float* A  = ta ? Wk : Wih;
    const float* Bm = ta ? Wq : Wv;
    int kbase = ks * 64;
    int tx = t & 15, ty = t >> 4;
    int mB = t & 63, kkb = t >> 6;
    int lm = t >> 2, lk = (t & 3) * 4;

    u64 c2[4][2];
    #pragma unroll
    for (int i = 0; i < 4; i++) { c2[i][0] = 0ull; c2[i][1] = 0ull; }

    float ar[4], br[4];
    float4 av;
    if (ta) {
        #pragma unroll
        for (int i = 0; i < 4; i++)
            ar[i] = A[(size_t)(kbase + kkb + 4 * i) * 256 + m0 + mB];
    } else {
        av = *(const float4*)&A[(size_t)(m0 + lm) * 256 + kbase + lk];
    }
    #pragma unroll
    for (int i = 0; i < 4; i++)
        br[i] = Bm[(size_t)(kbase + kkb + 4 * i) * 256 + n0 + mB];

    for (int ki = 0; ki < 4; ki++) {
        if (ta) {
            #pragma unroll
            for (int i = 0; i < 4; i++) As[kkb + 4 * i][mB] = ar[i];
        } else {
            As[lk + 0][lm] = av.x; As[lk + 1][lm] = av.y;
            As[lk + 2][lm] = av.z; As[lk + 3][lm] = av.w;
        }
        #pragma unroll
        for (int i = 0; i < 4; i++) Bs[kkb + 4 * i][mB] = br[i];
        __syncthreads();
        if (ki < 3) {
            int knext = kbase + (ki + 1) * 16;
            if (ta) {
                #pragma unroll
                for (int i = 0; i < 4; i++)
                    ar[i] = A[(size_t)(knext + kkb + 4 * i) * 256 + m0 + mB];
            } else {
                av = *(const float4*)&A[(size_t)(m0 + lm) * 256 + knext + lk];
            }
            #pragma unroll
            for (int i = 0; i < 4; i++)
                br[i] = Bm[(size_t)(knext + kkb + 4 * i) * 256 + n0 + mB];
        }
        #pragma unroll
        for (int kk = 0; kk < 16; kk++) {
            ulonglong2 w2 = *(const ulonglong2*)&Bs[kk][tx * 4];
            #pragma unroll
            for (int i = 0; i < 4; i++) {
                float ai = As[kk][ty * 4 + i];
                u64 a2 = pack2(ai, ai);
                c2[i][0] = fma2(a2, w2.x, c2[i][0]);
                c2[i][1] = fma2(a2, w2.y, c2[i][1]);
            }
        }
        __syncthreads();
    }

    size_t base = ((size_t)(ks * 64 + tile)) * 4096;
    #pragma unroll
    for (int i = 0; i < 4; i++) {
        #pragma unroll
        for (int p = 0; p < 2; p++) {
            float v0, v1;
            unpack2(c2[i][p], v0, v1);
            int off = (ty * 4 + i) * 64 + tx * 4 + 2 * p;
            partial[base + off]     = v0;
            partial[base + off + 1] = v1;
        }
    }
}

__global__ void prec_reduce_kernel(const float* __restrict__ partial,
                                   float* __restrict__ Wqk,
                                   float* __restrict__ Wiv) {
    int idx4 = blockIdx.x * 256 + threadIdx.x;
    int tile = idx4 >> 10;
    int w4 = (idx4 & 1023) * 4;
    const float* p = partial + (size_t)tile * 4096 + w4;
    float4 s = *(const float4*)p;
    #pragma unroll
    for (int ks = 1; ks < 4; ks++) {
        float4 v = *(const float4*)(p + (size_t)ks * 64 * 4096);
        s.x += v.x; s.y += v.y; s.z += v.z; s.w += v.w;
    }
    int i = w4 >> 6, j = w4 & 63;
    if (tile < 16) {
        int m = (tile >> 2) * 64 + i, n = (tile & 3) * 64 + j;
        s.x *= SCALE; s.y *= SCALE; s.z *= SCALE; s.w *= SCALE;
        *(float4*)&Wqk[(size_t)m * 256 + n] = s;
    } else {
        int t2 = tile - 16;
        int m = (t2 >> 2) * 64 + i, n = (t2 & 3) * 64 + j;
        *(float4*)&Wiv[(size_t)m * 256 + n] = s;
    }
}

// ---- shared gemm body ----------------------------------------------------
__device__ __forceinline__ void gemm_body(
    const float* __restrict__ A, const float* __restrict__ W,
    const float* __restrict__ bias, const float* __restrict__ extraM,
    const float* __restrict__ rvec, const float* __restrict__ cvec,
    float* __restrict__ C, int Nn, int K, int mode,
    float* As, float* Ws) {
    int t = threadIdx.x, tx = t & 15, ty = t >> 4;
    int m0 = blockIdx.y * 64, n0 = blockIdx.x * 64;
    int lm = t >> 2, lk = (t & 3) * 4;
    u64 c2[4][2];
    #pragma unroll
    for (int i = 0; i < 4; i++) { c2[i][0] = 0ull; c2[i][1] = 0ull; }

    float4 av = *(const float4*)&A[(size_t)(m0 + lm) * K + lk];
    float4 wv = *(const float4*)&W[(size_t)(n0 + lm) * K + lk];

    for (int k0 = 0; k0 < K; k0 += 16) {
        As[(lk + 0) * 68 + lm] = av.x; As[(lk + 1) * 68 + lm] = av.y;
        As[(lk + 2) * 68 + lm] = av.z; As[(lk + 3) * 68 + lm] = av.w;
        Ws[(lk + 0) * 68 + lm] = wv.x; Ws[(lk + 1) * 68 + lm] = wv.y;
        Ws[(lk + 2) * 68 + lm] = wv.z; Ws[(lk + 3) * 68 + lm] = wv.w;
        __syncthreads();
        if (k0 + 16 < K) {
            av = *(const float4*)&A[(size_t)(m0 + lm) * K + k0 + 16 + lk];
            wv = *(const float4*)&W[(size_t)(n0 + lm) * K + k0 + 16 + lk];
        }
        #pragma unroll
        for (int kk = 0; kk < 16; kk++) {
            float4 a = *(const float4*)&As[kk * 68 + ty * 4];
            ulonglong2 w2 = *(const ulonglong2*)&Ws[kk * 68 + tx * 4];
            float arr[4] = {a.x, a.y, a.z, a.w};
            #pragma unroll
            for (int i = 0; i < 4; i++) {
                u64 a2 = pack2(arr[i], arr[i]);
                c2[i][0] = fma2(a2, w2.x, c2[i][0]);
                c2[i][1] = fma2(a2, w2.y, c2[i][1]);
            }
        }
        __syncthreads();
    }
    #pragma unroll
    for (int i = 0; i < 4; i++) {
        int r = m0 + ty * 4 + i;
        #pragma unroll
        for (int p = 0; p < 2; p++) {
            float v0, v1;
            unpack2(c2[i][p], v0, v1);
            int c0c = n0 + tx * 4 + 2 * p;
            v0 += bias[c0c]; v1 += bias[c0c + 1];
            if (mode == 1) { v0 = fmaxf(v0, 0.0f); v1 = fmaxf(v1, 0.0f); }
            if (mode == 2) {
                v0 += extraM[(size_t)r * Nn + c0c];
                v1 += extraM[(size_t)r * Nn + c0c + 1];
            }
            if (mode == 3) {
                float rv = rvec[r];
                v0 += rv * cvec[c0c]; v1 += rv * cvec[c0c + 1];
            }
            C[(size_t)r * Nn + c0c]     = v0;
            C[(size_t)r * Nn + c0c + 1] = v1;
        }
    }
}

__global__ __launch_bounds__(256) void gigh_kernel(
    const float* __restrict__ uv, const float* __restrict__ slots,
    const float* __restrict__ Wiv, const float* __restrict__ Whh,
    const float* __restrict__ bih, const float* __restrict__ bhh,
    const float* __restrict__ r, const float* __restrict__ biv,
    float* __restrict__ gi, float* __restrict__ gh) {
    __shared__ float As[16 * 68];
    __shared__ float Ws[16 * 68];
    if (blockIdx.z == 0)
        gemm_body(uv, Wiv, bih, nullptr, r, biv, gi, 3 * D_, DIN, 3, As, Ws);
    else
        gemm_body(slots, Whh, bhh, nullptr, nullptr, nullptr, gh, 3 * D_, D_, 0, As, Ws);
}

__global__ __launch_bounds__(256) void mlp1_kernel(
    const float* __restrict__ m, const float* __restrict__ W1,
    const float* __restrict__ b1, float* __restrict__ t) {
    __shared__ float As[16 * 68];
    __shared__ float Ws[16 * 68];
    gemm_body(m, W1, b1, nullptr, nullptr, nullptr, t, H_, D_, 1, As, Ws);
}

__global__ __launch_bounds__(256) void mlp2_kernel(
    const float* __restrict__ t, const float* __restrict__ W2,
    const float* __restrict__ b2, const float* __restrict__ h,
    float* __restrict__ outp) {
    __shared__ float As[16 * 68];
    __shared__ float Ws[16 * 68];
    gemm_body(t, W2, b2, h, nullptr, nullptr, outp, D_, H_, 2, As, Ws);
}

// ------- front: LN(slots) -> qk gemm (+bqk) and ct ------------------------
#define FRONT_SMEM ((64 * XS + 16 * 68) * 4)
__global__ __launch_bounds__(256) void front_kernel(
    const float* __restrict__ slots,
    const float* __restrict__ ln_g, const float* __restrict__ ln_b,
    const float* __restrict__ Wqk, const float* __restrict__ bqk,
    const float* __restrict__ us, const float* __restrict__ c0,
    float* __restrict__ qk, float* __restrict__ ct) {
    extern __shared__ float sm[];
    float* snS = sm;
    float* Ws  = sm + 64 * XS;
    int t = threadIdx.x, w = t >> 5, lane = t & 31;
    int r0 = blockIdx.y * 64, c0b = blockIdx.x * 64;

    const float4* g4 = (const float4*)ln_g;
    const float4* b4 = (const float4*)ln_b;
    float4 ga = g4[lane], gc = g4[lane + 32];
    float4 ba = b4[lane], bc = b4[lane + 32];
    for (int rr = 0; rr < 8; rr++) {
        int lr = w * 8 + rr;
        const float4* x4 = (const float4*)(slots + (size_t)(r0 + lr) * 256);
        float4 a = x4[lane], c = x4[lane + 32];
        float s  = a.x + a.y + a.z + a.w + c.x + c.y + c.z + c.w;
        float s2 = a.x*a.x + a.y*a.y + a.z*a.z + a.w*a.w
                 + c.x*c.x + c.y*c.y + c.z*c.z + c.w*c.w;
        #pragma unroll
        for (int o = 16; o; o >>= 1) {
            s  += __shfl_xor_sync(0xffffffffu, s,  o);
            s2 += __shfl_xor_sync(0xffffffffu, s2, o);
        }
        float mean = s * (1.0f / 256.0f);
        float var  = s2 * (1.0f / 256.0f) - mean * mean;
        float rstd = rsqrtf(var + EPS);
        float4 o1, o2;
        o1.x = (a.x - mean) * rstd * ga.x + ba.x;
        o1.y = (a.y - mean) * rstd * ga.y + ba.y;
        o1.z = (a.z - mean) * rstd * ga.z + ba.z;
        o1.w = (a.w - mean) * rstd * ga.w + ba.w;
        o2.x = (c.x - mean) * rstd * gc.x + bc.x;
        o2.y = (c.y - mean) * rstd * gc.y + bc.y;
        o2.z = (c.z - mean) * rstd * gc.z + bc.z;
        o2.w = (c.w - mean) * rstd * gc.w + bc.w;
        *(float4*)&snS[lr * XS + lane * 4] = o1;
        *(float4*)&snS[lr * XS + (lane + 32) * 4] = o2;
    }
    __syncthreads();

    if (blockIdx.x == 0 && t < 64) {
        float s = 0.0f;
        #pragma unroll 8
        for (int e = 0; e < 256; e++) s += snS[t * XS + e] * us[e];
        ct[r0 + t] = s + c0[0];
    }
    __syncthreads();

    int tx = t & 15, ty = t >> 4, lm = t >> 2, lk = (t & 3) * 4;
    u64 c2[4][2];
    #pragma unroll
    for (int i = 0; i < 4; i++) { c2[i][0] = 0ull; c2[i][1] = 0ull; }
    float4 wv = *(const float4*)&Wqk[(size_t)(c0b + lm) * 256 + lk];
    for (int k0 = 0; k0 < 256; k0 += 16) {
        Ws[(lk + 0) * 68 + lm] = wv.x; Ws[(lk + 1) * 68 + lm] = wv.y;
        Ws[(lk + 2) * 68 + lm] = wv.z; Ws[(lk + 3) * 68 + lm] = wv.w;
        __syncthreads();
        if (k0 + 16 < 256)
            wv = *(const float4*)&Wqk[(size_t)(c0b + lm) * 256 + k0 + 16 + lk];
        #pragma unroll
        for (int kk = 0; kk < 16; kk++) {
            ulonglong2 w2 = *(const ulonglong2*)&Ws[kk * 68 + tx * 4];
            #pragma unroll
            for (int i = 0; i < 4; i++) {
                float ai = snS[(ty * 4 + i) * XS + k0 + kk];
                u64 a2 = pack2(ai, ai);
                c2[i][0] = fma2(a2, w2.x, c2[i][0]);
                c2[i][1] = fma2(a2, w2.y, c2[i][1]);
            }
        }
        __syncthreads();
    }
    #pragma unroll
    for (int i = 0; i < 4; i++) {
        int r = r0 + ty * 4 + i;
        #pragma unroll
        for (int p = 0; p < 2; p++) {
            float v0, v1;
            unpack2(c2[i][p], v0, v1);
            int cc = c0b + tx * 4 + 2 * p;
            qk[(size_t)r * 256 + cc]     = v0 + bqk[cc];
            qk[(size_t)r * 256 + cc + 1] = v1 + bqk[cc + 1];
        }
    }
}

// --------- fused: 16 subtiles (32 rows), cp.async double-buffered ---------
// smem floats: xsm0 32*XS | xsm1 32*XS | qsm 4096 | red 7*512 | atsm 32*AS | csm 16 | wred 16
#define FUSED_SMEM ((2 * RSUB * XS + 16 * 256 + 7 * 512 + RSUB * AS + 32) * 4)

__global__ __launch_bounds__(256, 2) void fused_attn_kernel(
    const float* __restrict__ X, const float* __restrict__ QK,
    const float* __restrict__ CT,
    float* __restrict__ part, float* __restrict__ rpart,
    float* __restrict__ attn_out) {
    extern __shared__ float sm[];
    float* xsmA = sm;                       // [32][XS]
    float* xsmB = sm + RSUB * XS;           // [32][XS]
    float* qsm  = sm + 2 * RSUB * XS;       // [16][256]
    float* red  = qsm + 16 * 256;           // [7][16][32]
    float* atsm = red + 7 * 512;            // [32][AS]
    float* csm  = atsm + RSUB * AS;         // [16]
    float* wred = csm + 16;                 // [16]
    int b = blockIdx.y, grp = blockIdx.x;
    int tid = threadIdx.x;
    int n5 = tid & 31, dq = tid >> 5;       // dq 0..7, warp-uniform
    int db = dq * 32;

    for (int e = tid; e < S_ * 64; e += 256) {
        int s = e >> 6, c4 = (e & 63) * 4;
        *(float4*)&qsm[s * 256 + c4] =
            *(const float4*)&QK[((size_t)b * S_ + s) * DIN + c4];
    }
    if (tid < S_) csm[tid] = CT[b * S_ + tid];

    uint32_t xb32[2];
    xb32[0] = (uint32_t)__cvta_generic_to_shared(xsmA);
    xb32[1] = (uint32_t)__cvta_generic_to_shared(xsmB);

    // prologue: issue subtiles 0, 1
    #pragma unroll
    for (int t0 = 0; t0 < 2; t0++) {
        const float* xb = X + ((size_t)b * N_ + grp * 512 + t0 * RSUB) * DIN;
        #pragma unroll
        for (int j = 0; j < 8; j++) {
            int e = tid + j * 256;
            int row = e >> 6, c4 = e & 63;
            cp_async16(xb32[t0] + (uint32_t)(row * XS + c4 * 4) * 4,
                       xb + (size_t)row * DIN + c4 * 4);
        }
        cp_commit();
    }

    u64 uacc[8];
    #pragma unroll
    for (int sp = 0; sp < 8; sp++) uacc[sp] = 0ull;
    float rtot = 0.0f;

    for (int st = 0; st < SUBS; st++) {
        float* xs = (st & 1) ? xsmB : xsmA;
        int n0 = grp * 512 + st * RSUB;
        cp_wait1();
        __syncthreads();   // subtile st visible; (st==0) qsm/csm visible

        // ---- phase 1: logits[n5][s] over 32-d chunk ----
        u64 acc[S_];
        #pragma unroll
        for (int s = 0; s < S_; s++) acc[s] = 0ull;
        const ulonglong2* xr = (const ulonglong2*)(xs + n5 * XS + db);
        #pragma unroll
        for (int i = 0; i < 8; i++) {
            ulonglong2 xv = xr[i];
            const float* qb = qsm + db + i * 4;
            #pragma unroll
            for (int s = 0; s < S_; s++) {
                ulonglong2 qv = *(const ulonglong2*)(qb + s * 256);
                acc[s] = fma2(xv.x, qv.x, acc[s]);
                acc[s] = fma2(xv.y, qv.y, acc[s]);
            }
        }
        float p[S_];
        #pragma unroll
        for (int s = 0; s < S_; s++) p[s] = hsum2(acc[s]);

        if (dq > 0) {
            float* base = red + (dq - 1) * 512;
            #pragma unroll
            for (int s = 0; s < S_; s++) base[s * 32 + n5] = p[s];
        }
        __syncthreads();

        // ---- softmax (warp 0, one thread per n) + rowsum ----
        if (dq == 0) {
            #pragma unroll
            for (int s = 0; s < S_; s++) {
                float v = p[s];
                #pragma unroll
                for (int j = 0; j < 7; j++) v += red[j * 512 + s * 32 + n5];
                p[s] = v + csm[s];
            }
            float mx = -1e30f;
            #pragma unroll
            for (int s = 0; s < S_; s++) mx = fmaxf(mx, p[s]);
            float sum = 0.0f;
            #pragma unroll
            for (int s = 0; s < S_; s++) { p[s] = __expf(p[s] - mx); sum += p[s]; }
            float inv = 1.0f / sum;
            #pragma unroll
            for (int s = 0; s < S_; s++) {
                float a = p[s] * inv;
                p[s] = a;
                atsm[n5 * AS + s] = a;
                if (attn_out)
                    attn_out[((size_t)(b * S_ + s)) * N_ + n0 + n5] = a;
            }
            #pragma unroll
            for (int s = 0; s < S_; s++) {
                float v = p[s];
                #pragma unroll
                for (int o = 16; o; o >>= 1) v += __shfl_xor_sync(0xffffffffu, v, o);
                if (n5 == 0) wred[s] = v;
            }
        }
        __syncthreads();
        if (tid < S_) rtot += wred[tid];

        // ---- phase 3: accumulate uv over this subtile's 32 n ----
        #pragma unroll 4
        for (int nn = 0; nn < RSUB; nn++) {
            float xv = xs[nn * XS + tid];
            u64 x2 = pack2(xv, xv);
            const ulonglong2* arow2 = (const ulonglong2*)(atsm + nn * AS);
            #pragma unroll
            for (int jj = 0; jj < 4; jj++) {
                ulonglong2 ap = arow2[jj];
                uacc[2 * jj]     = fma2(x2, ap.x, uacc[2 * jj]);
                uacc[2 * jj + 1] = fma2(x2, ap.y, uacc[2 * jj + 1]);
            }
        }
        __syncthreads();   // reads of xs/atsm done -> safe to refill

        // ---- refill this buffer with subtile st+2 ----
        int tn = st + 2;
        if (tn < SUBS) {
            const float* xb = X + ((size_t)b * N_ + grp * 512 + tn * RSUB) * DIN;
            #pragma unroll
            for (int j = 0; j < 8; j++) {
                int e = tid + j * 256;
                int row = e >> 6, c4 = e & 63;
                cp_async16(xb32[st & 1] + (uint32_t)(row * XS + c4 * 4) * 4,
                           xb + (size_t)row * DIN + c4 * 4);
            }
        }
        cp_commit();
    }

    float* po = part + ((size_t)(b * NGRP + grp) * S_) * DIN + tid;
    #pragma unroll
    for (int sp = 0; sp < 8; sp++) {
        float v0, v1;
        unpack2(uacc[sp], v0, v1);
        po[(size_t)(2 * sp) * DIN]     = v0;
        po[(size_t)(2 * sp + 1) * DIN] = v1;
    }
    if (tid < S_)
        rpart[((size_t)b * NGRP + grp) * S_ + tid] = rtot;
}

// ---------------- merged reductions (float4, 8-way) -----------------------
__global__ void reduce_kernel(const float* __restrict__ part,
                              const float* __restrict__ rpart,
                              float* __restrict__ uv,
                              float* __restrict__ r) {
    int idx4 = blockIdx.x * 256 + threadIdx.x;     // 0..32767
    int b = idx4 >> 10;
    int sd4 = (idx4 & 1023) * 4;
    const float* p = part + (size_t)b * NGRP * 4096 + sd4;
    float4 s = make_float4(0.f, 0.f, 0.f, 0.f);
    #pragma unroll
    for (int t = 0; t < NGRP; t++) {
        float4 v = *(const float4*)(p + (size_t)t * 4096);
        s.x += v.x; s.y += v.y; s.z += v.z; s.w += v.w;
    }
    *(float4*)&uv[(size_t)idx4 * 4] = s;
    if (blockIdx.x == 0) {
        for (int i = threadIdx.x; i < ROWS; i += 256) {
            const float* rp = rpart + (i >> 4) * NGRP * S_ + (i & 15);
            float v = 0.0f;
            #pragma unroll
            for (int t = 0; t < NGRP; t++) v += rp[t * S_];
            r[i] = v;
        }
    }
}

// ---------------- GRU + LN(m) fused (warp per row) ------------------------
__global__ void gru_ln_kernel(const float* __restrict__ gi,
                              const float* __restrict__ gh,
                              const float* __restrict__ slots,
                              const float* __restrict__ gg,
                              const float* __restrict__ bb,
                              float* __restrict__ h,
                              float* __restrict__ m) {
    int w = threadIdx.x >> 5, lane = threadIdx.x & 31;
    int row = blockIdx.x * 8 + w;
    const float* gir = gi + (size_t)row * 768;
    const float* ghr = gh + (size_t)row * 768;
    const float* hp  = slots + (size_t)row * 256;
    int c1 = lane * 4, c2i = c1 + 128;
    float hv[8];
    #pragma unroll
    for (int g = 0; g < 2; g++) {
        int c = g ? c2i : c1;
        float4 ir = *(const float4*)&gir[c];
        float4 hr = *(const float4*)&ghr[c];
        float4 iz = *(const float4*)&gir[c + 256];
        float4 hz = *(const float4*)&ghr[c + 256];
        float4 in = *(const float4*)&gir[c + 512];
        float4 hn = *(const float4*)&ghr[c + 512];
        float4 pv = *(const float4*)&hp[c];
        float rr, zz, nn;
        rr = sigmoidf(ir.x + hr.x); zz = sigmoidf(iz.x + hz.x);
        nn = tanhf(in.x + rr * hn.x); hv[g*4+0] = (1.0f - zz) * nn + zz * pv.x;
        rr = sigmoidf(ir.y + hr.y); zz = sigmoidf(iz.y + hz.y);
        nn = tanhf(in.y + rr * hn.y); hv[g*4+1] = (1.0f - zz) * nn + zz * pv.y;
        rr = sigmoidf(ir.z + hr.z); zz = sigmoidf(iz.z + hz.z);
        nn = tanhf(in.z + rr * hn.z); hv[g*4+2] = (1.0f - zz) * nn + zz * pv.z;
        rr = sigmoidf(ir.w + hr.w); zz = sigmoidf(iz.w + hz.w);
        nn = tanhf(in.w + rr * hn.w); hv[g*4+3] = (1.0f - zz) * nn + zz * pv.w;
    }
    float s = 0.0f, s2 = 0.0f;
    #pragma unroll
    for (int i = 0; i < 8; i++) { s += hv[i]; s2 += hv[i] * hv[i]; }
    #pragma unroll
    for (int o = 16; o; o >>= 1) {
        s  += __shfl_xor_sync(0xffffffffu, s,  o);
        s2 += __shfl_xor_sync(0xffffffffu, s2, o);
    }
    float mean = s * (1.0f / 256.0f);
    float var  = s2 * (1.0f / 256.0f) - mean * mean;
    float rstd = rsqrtf(var + EPS);
    float* hrow = h + (size_t)row * 256;
    float* mrow = m + (size_t)row * 256;
    #pragma unroll
    for (int g = 0; g < 2; g++) {
        int c = g ? c2i : c1;
        float4 gv = *(const float4*)&gg[c];
        float4 bv = *(const float4*)&bb[c];
        float4 hvv = make_float4(hv[g*4+0], hv[g*4+1], hv[g*4+2], hv[g*4+3]);
        float4 mv;
        mv.x = (hvv.x - mean) * rstd * gv.x + bv.x;
        mv.y = (hvv.y - mean) * rstd * gv.y + bv.y;
        mv.z = (hvv.z - mean) * rstd * gv.z + bv.z;
        mv.w = (hvv.w - mean) * rstd * gv.w + bv.w;
        *(float4*)&hrow[c] = hvv;
        *(float4*)&mrow[c] = mv;
    }
}

// ---------------- host side ------------------------------------------------
extern "C" void kernel_launch(void* const* d_in, const int* in_sizes, int n_in,
                              void* d_out, int out_size) {
    const float* inputs     = (const float*)d_in[0];
    const float* init_noise = (const float*)d_in[1];
    const float* slots_mu   = (const float*)d_in[2];
    const float* slots_sig  = (const float*)d_in[3];
    const float* ln_in_g    = (const float*)d_in[4];
    const float* ln_in_b    = (const float*)d_in[5];
    const float* ln_s_g     = (const float*)d_in[6];
    const float* ln_s_b     = (const float*)d_in[7];
    const float* ln_m_g     = (const float*)d_in[8];
    const float* ln_m_b     = (const float*)d_in[9];
    const float* Wk         = (const float*)d_in[10];
    const float* bk         = (const float*)d_in[11];
    const float* Wv         = (const float*)d_in[12];
    const float* bv         = (const float*)d_in[13];
    const float* Wq         = (const float*)d_in[14];
    const float* bq         = (const float*)d_in[15];
    const float* W_ih       = (const float*)d_in[16];
    const float* W_hh       = (const float*)d_in[17];
    const float* b_ih       = (const float*)d_in[18];
    const float* b_hh       = (const float*)d_in[19];
    const float* W1         = (const float*)d_in[20];
    const float* b1         = (const float*)d_in[21];
    const float* W2         = (const float*)d_in[22];
    const float* b2         = (const float*)d_in[23];
    float* out = (float*)d_out;

    float *xln, *slots, *qk, *ct, *uv, *r, *part, *rpart;
    float *gi, *gh, *h, *m, *t, *Wqk, *Wiv, *us, *bqk, *biv, *c0, *prec;
    cudaGetSymbolAddress((void**)&xln,   g_xln);
    cudaGetSymbolAddress((void**)&slots, g_slots);
    cudaGetSymbolAddress((void**)&qk,    g_qk);
    cudaGetSymbolAddress((void**)&ct,    g_ct);
    cudaGetSymbolAddress((void**)&uv,    g_uv);
    cudaGetSymbolAddress((void**)&r,     g_r);
    cudaGetSymbolAddress((void**)&part,  g_part);
    cudaGetSymbolAddress((void**)&rpart, g_rpart);
    cudaGetSymbolAddress((void**)&gi,    g_gi);
    cudaGetSymbolAddress((void**)&gh,    g_gh);
    cudaGetSymbolAddress((void**)&h,     g_h);
    cudaGetSymbolAddress((void**)&m,     g_m);
    cudaGetSymbolAddress((void**)&t,     g_t);
    cudaGetSymbolAddress((void**)&Wqk,   g_Wqk);
    cudaGetSymbolAddress((void**)&Wiv,   g_Wiv);
    cudaGetSymbolAddress((void**)&us,    g_us);
    cudaGetSymbolAddress((void**)&bqk,   g_bqk);
    cudaGetSymbolAddress((void**)&biv,   g_biv);
    cudaGetSymbolAddress((void**)&c0,    g_c0);
    cudaGetSymbolAddress((void**)&prec,  g_prec);

    cudaFuncSetAttribute(fused_attn_kernel,
                         cudaFuncAttributeMaxDynamicSharedMemorySize, FUSED_SMEM);
    cudaFuncSetAttribute(front_kernel,
                         cudaFuncAttributeMaxDynamicSharedMemorySize, FRONT_SMEM);

    const int BND = B_ * N_;
    const int BSD = ROWS * D_;      // 131072
    const int BSN = B_ * S_ * N_;   // 2097152

    // prologue
    slots_init_kernel<<<BSD / 256, 256>>>(init_noise, slots_mu, slots_sig, slots);
    ln_rows_kernel<<<BND / 8, 256>>>(inputs, ln_in_g, ln_in_b, xln, BND);
    prec_kernel<<<dim3(162, 4), 256>>>(Wk, Wq, W_ih, Wv, bk, bq, bv,
                                       prec, us, bqk, c0, biv);
    prec_reduce_kernel<<<256, 256>>>(prec, Wqk, Wiv);

    float* attn_out = out + (out_size - BSN);

    for (int it = 0; it < 3; it++) {
        front_kernel<<<dim3(DIN / 64, ROWS / 64), 256, FRONT_SMEM>>>(
            slots, ln_s_g, ln_s_b, Wqk, bqk, us, c0, qk, ct);
        fused_attn_kernel<<<dim3(NGRP, B_), 256, FUSED_SMEM>>>(
            xln, qk, ct, part, rpart, (it == 2) ? attn_out : nullptr);
        reduce_kernel<<<(ROWS * DIN) / 1024, 256>>>(part, rpart, uv, r);
        gigh_kernel<<<dim3((3 * D_) / 64, ROWS / 64, 2), 256>>>(
            uv, slots, Wiv, W_hh, b_ih, b_hh, r, biv, gi, gh);
        gru_ln_kernel<<<ROWS / 8, 256>>>(gi, gh, slots, ln_m_g, ln_m_b, h, m);
        mlp1_kernel<<<dim3(H_ / 64, ROWS / 64), 256>>>(m, W1, b1, t);
        mlp2_kernel<<<dim3(D_ / 64, ROWS / 64), 256>>>(
            t, W2, b2, h, (it == 2) ? out : slots);
    }
}

// round 12
// speedup vs baseline: 1.0659x; 1.0659x over previous
#include <cuda_runtime.h>
#include <cstddef>
#include <cstdint>

#define B_  32
#define N_  4096
#define DIN 256
#define D_  256
#define S_  16
#define H_  512
#define EPS 1e-5f
#define SCALE 0.0625f
#define NB 64
#define GRP 8                // tiles per fused block
#define NGRP 8               // groups per batch
#define XS 260               // xsm row stride (floats)
#define AS 20                // atsm row stride
#define ROWS (B_*S_)         // 512

typedef unsigned long long u64;

__device__ __forceinline__ u64 fma2(u64 a, u64 b, u64 c) {
    u64 d;
    asm("fma.rn.f32x2 %0, %1, %2, %3;" : "=l"(d) : "l"(a), "l"(b), "l"(c));
    return d;
}
__device__ __forceinline__ u64 pack2(float lo, float hi) {
    u64 d;
    asm("mov.b64 %0, {%1, %2};" : "=l"(d) : "f"(lo), "f"(hi));
    return d;
}
__device__ __forceinline__ void unpack2(u64 v, float& lo, float& hi) {
    asm("mov.b64 {%0, %1}, %2;" : "=f"(lo), "=f"(hi) : "l"(v));
}
__device__ __forceinline__ float hsum2(u64 v) {
    float a, b; unpack2(v, a, b); return a + b;
}
__device__ __forceinline__ float sigmoidf(float x) { return 1.0f / (1.0f + __expf(-x)); }

// ---------------- scratch ----------------
__device__ float g_slots[ROWS * D_];
__device__ float g_qk   [ROWS * DIN];
__device__ float g_ct   [ROWS];
__device__ float g_uv   [ROWS * DIN];
__device__ float g_r    [ROWS];
__device__ float g_part [(size_t)B_ * NGRP * S_ * DIN];   // 2.1 MB
__device__ float g_rpart[B_ * NGRP * S_];
__device__ float g_gi   [ROWS * 3 * D_];
__device__ float g_gh   [ROWS * 3 * D_];
__device__ float g_h    [ROWS * D_];
__device__ float g_m    [ROWS * D_];
__device__ float g_t    [ROWS * H_];
__device__ float g_Wqk  [DIN * D_];
__device__ float g_Wiv  [3 * D_ * DIN];
__device__ float g_us   [D_];
__device__ float g_bqk  [DIN];
__device__ float g_biv  [3 * D_];
__device__ float g_c0   [1];
__device__ float g_prec [4 * 64 * 4096];

// ---------------- slots init ----------------
__global__ void slots_init_kernel(const float* __restrict__ noise,
                                  const float* __restrict__ mu,
                                  const float* __restrict__ sigma,
                                  float* __restrict__ slots) {
    int i = blockIdx.x * 256 + threadIdx.x;
    int d = i & (D_ - 1);
    slots[i] = mu[d] + sigma[d] * noise[i];
}

// ------------- combined split-k precompute + prep -------------------------
__global__ __launch_bounds__(256) void prec_kernel(
    const float* __restrict__ Wk, const float* __restrict__ Wq,
    const float* __restrict__ Wih, const float* __restrict__ Wv,
    const float* __restrict__ bk, const float* __restrict__ bq,
    const float* __restrict__ bv,
    float* __restrict__ partial,
    float* __restrict__ us, float* __restrict__ bqk,
    float* __restrict__ c0, float* __restrict__ biv) {
    int t = threadIdx.x;
    int tile = blockIdx.x, ks = blockIdx.y;

    if (tile >= 64) {
        if (ks != 0) return;
        int bx = tile - 64;
        if (bx < 96) {
            int warp = t >> 5, lane = t & 31;
            int r = bx * 8 + warp;
            float s = 0.0f;
            #pragma unroll
            for (int e = lane; e < D_; e += 32) s += Wih[(size_t)r * D_ + e] * bv[e];
            #pragma unroll
            for (int o = 16; o; o >>= 1) s += __shfl_xor_sync(0xffffffffu, s, o);
            if (lane == 0) biv[r] = s;
        } else if (bx == 96) {
            float s = 0.0f;
            for (int e = 0; e < D_; e++) s += bk[e] * Wq[(size_t)e * D_ + t];
            us[t] = SCALE * s;
            if (t == 0) {
                float c = 0.0f;
                for (int e = 0; e < D_; e++) c += bk[e] * bq[e];
                *c0 = SCALE * c;
            }
        } else {
            float s = 0.0f;
            for (int e = 0; e < D_; e++) s += bq[e] * Wk[(size_t)e * DIN + t];
            bqk[t] = SCALE * s;
        }
        return;
    }

    __shared__ float As[16][68];
    __shared__ float Bs[16][68];
    bool ta = (tile < 16);
    int t2 = ta ? tile : tile - 16;
    int m0 = (t2 >> 2) * 64, n0 = (t2 & 3) * 64;
    const float* A  = ta ? Wk : Wih;
    const float* Bm = ta ? Wq : Wv;
    int kbase = ks * 64;
    int tx = t & 15, ty = t >> 4;
    int mB = t & 63, kkb = t >> 6;
    int lm = t >> 2, lk = (t & 3) * 4;

    u64 c2[4][2];
    #pragma unroll
    for (int i = 0; i < 4; i++) { c2[i][0] = 0ull; c2[i][1] = 0ull; }

    float ar[4], br[4];
    float4 av;
    if (ta) {
        #pragma unroll
        for (int i = 0; i < 4; i++)
            ar[i] = A[(size_t)(kbase + kkb + 4 * i) * 256 + m0 + mB];
    } else {
        av = *(const float4*)&A[(size_t)(m0 + lm) * 256 + kbase + lk];
    }
    #pragma unroll
    for (int i = 0; i < 4; i++)
        br[i] = Bm[(size_t)(kbase + kkb + 4 * i) * 256 + n0 + mB];

    for (int ki = 0; ki < 4; ki++) {
        if (ta) {
            #pragma unroll
            for (int i = 0; i < 4; i++) As[kkb + 4 * i][mB] = ar[i];
        } else {
            As[lk + 0][lm] = av.x; As[lk + 1][lm] = av.y;
            As[lk + 2][lm] = av.z; As[lk + 3][lm] = av.w;
        }
        #pragma unroll
        for (int i = 0; i < 4; i++) Bs[kkb + 4 * i][mB] = br[i];
        __syncthreads();
        if (ki < 3) {
            int knext = kbase + (ki + 1) * 16;
            if (ta) {
                #pragma unroll
                for (int i = 0; i < 4; i++)
                    ar[i] = A[(size_t)(knext + kkb + 4 * i) * 256 + m0 + mB];
            } else {
                av = *(const float4*)&A[(size_t)(m0 + lm) * 256 + knext + lk];
            }
            #pragma unroll
            for (int i = 0; i < 4; i++)
                br[i] = Bm[(size_t)(knext + kkb + 4 * i) * 256 + n0 + mB];
        }
        #pragma unroll
        for (int kk = 0; kk < 16; kk++) {
            ulonglong2 w2 = *(const ulonglong2*)&Bs[kk][tx * 4];
            #pragma unroll
            for (int i = 0; i < 4; i++) {
                float ai = As[kk][ty * 4 + i];
                u64 a2 = pack2(ai, ai);
                c2[i][0] = fma2(a2, w2.x, c2[i][0]);
                c2[i][1] = fma2(a2, w2.y, c2[i][1]);
            }
        }
        __syncthreads();
    }

    size_t base = ((size_t)(ks * 64 + tile)) * 4096;
    #pragma unroll
    for (int i = 0; i < 4; i++) {
        #pragma unroll
        for (int p = 0; p < 2; p++) {
            float v0, v1;
            unpack2(c2[i][p], v0, v1);
            int off = (ty * 4 + i) * 64 + tx * 4 + 2 * p;
            partial[base + off]     = v0;
            partial[base + off + 1] = v1;
        }
    }
}

__global__ void prec_reduce_kernel(const float* __restrict__ partial,
                                   float* __restrict__ Wqk,
                                   float* __restrict__ Wiv) {
    int idx4 = blockIdx.x * 256 + threadIdx.x;
    int tile = idx4 >> 10;
    int w4 = (idx4 & 1023) * 4;
    const float* p = partial + (size_t)tile * 4096 + w4;
    float4 s = *(const float4*)p;
    #pragma unroll
    for (int ks = 1; ks < 4; ks++) {
        float4 v = *(const float4*)(p + (size_t)ks * 64 * 4096);
        s.x += v.x; s.y += v.y; s.z += v.z; s.w += v.w;
    }
    int i = w4 >> 6, j = w4 & 63;
    if (tile < 16) {
        int m = (tile >> 2) * 64 + i, n = (tile & 3) * 64 + j;
        s.x *= SCALE; s.y *= SCALE; s.z *= SCALE; s.w *= SCALE;
        *(float4*)&Wqk[(size_t)m * 256 + n] = s;
    } else {
        int t2 = tile - 16;
        int m = (t2 >> 2) * 64 + i, n = (t2 & 3) * 64 + j;
        *(float4*)&Wiv[(size_t)m * 256 + n] = s;
    }
}

// ---- shared gemm body ----------------------------------------------------
__device__ __forceinline__ void gemm_body(
    const float* __restrict__ A, const float* __restrict__ W,
    const float* __restrict__ bias, const float* __restrict__ extraM,
    const float* __restrict__ rvec, const float* __restrict__ cvec,
    float* __restrict__ C, int Nn, int K, int mode,
    float* As, float* Ws) {
    int t = threadIdx.x, tx = t & 15, ty = t >> 4;
    int m0 = blockIdx.y * 64, n0 = blockIdx.x * 64;
    int lm = t >> 2, lk = (t & 3) * 4;
    u64 c2[4][2];
    #pragma unroll
    for (int i = 0; i < 4; i++) { c2[i][0] = 0ull; c2[i][1] = 0ull; }

    float4 av = *(const float4*)&A[(size_t)(m0 + lm) * K + lk];
    float4 wv = *(const float4*)&W[(size_t)(n0 + lm) * K + lk];

    for (int k0 = 0; k0 < K; k0 += 16) {
        As[(lk + 0) * 68 + lm] = av.x; As[(lk + 1) * 68 + lm] = av.y;
        As[(lk + 2) * 68 + lm] = av.z; As[(lk + 3) * 68 + lm] = av.w;
        Ws[(lk + 0) * 68 + lm] = wv.x; Ws[(lk + 1) * 68 + lm] = wv.y;
        Ws[(lk + 2) * 68 + lm] = wv.z; Ws[(lk + 3) * 68 + lm] = wv.w;
        __syncthreads();
        if (k0 + 16 < K) {
            av = *(const float4*)&A[(size_t)(m0 + lm) * K + k0 + 16 + lk];
            wv = *(const float4*)&W[(size_t)(n0 + lm) * K + k0 + 16 + lk];
        }
        #pragma unroll
        for (int kk = 0; kk < 16; kk++) {
            float4 a = *(const float4*)&As[kk * 68 + ty * 4];
            ulonglong2 w2 = *(const ulonglong2*)&Ws[kk * 68 + tx * 4];
            float arr[4] = {a.x, a.y, a.z, a.w};
            #pragma unroll
            for (int i = 0; i < 4; i++) {
                u64 a2 = pack2(arr[i], arr[i]);
                c2[i][0] = fma2(a2, w2.x, c2[i][0]);
                c2[i][1] = fma2(a2, w2.y, c2[i][1]);
            }
        }
        __syncthreads();
    }
    #pragma unroll
    for (int i = 0; i < 4; i++) {
        int r = m0 + ty * 4 + i;
        #pragma unroll
        for (int p = 0; p < 2; p++) {
            float v0, v1;
            unpack2(c2[i][p], v0, v1);
            int c0c = n0 + tx * 4 + 2 * p;
            v0 += bias[c0c]; v1 += bias[c0c + 1];
            if (mode == 1) { v0 = fmaxf(v0, 0.0f); v1 = fmaxf(v1, 0.0f); }
            if (mode == 2) {
                v0 += extraM[(size_t)r * Nn + c0c];
                v1 += extraM[(size_t)r * Nn + c0c + 1];
            }
            if (mode == 3) {
                float rv = rvec[r];
                v0 += rv * cvec[c0c]; v1 += rv * cvec[c0c + 1];
            }
            C[(size_t)r * Nn + c0c]     = v0;
            C[(size_t)r * Nn + c0c + 1] = v1;
        }
    }
}

__global__ __launch_bounds__(256) void gigh_kernel(
    const float* __restrict__ uv, const float* __restrict__ slots,
    const float* __restrict__ Wiv, const float* __restrict__ Whh,
    const float* __restrict__ bih, const float* __restrict__ bhh,
    const float* __restrict__ r, const float* __restrict__ biv,
    float* __restrict__ gi, float* __restrict__ gh) {
    __shared__ float As[16 * 68];
    __shared__ float Ws[16 * 68];
    if (blockIdx.z == 0)
        gemm_body(uv, Wiv, bih, nullptr, r, biv, gi, 3 * D_, DIN, 3, As, Ws);
    else
        gemm_body(slots, Whh, bhh, nullptr, nullptr, nullptr, gh, 3 * D_, D_, 0, As, Ws);
}

__global__ __launch_bounds__(256) void mlp1_kernel(
    const float* __restrict__ m, const float* __restrict__ W1,
    const float* __restrict__ b1, float* __restrict__ t) {
    __shared__ float As[16 * 68];
    __shared__ float Ws[16 * 68];
    gemm_body(m, W1, b1, nullptr, nullptr, nullptr, t, H_, D_, 1, As, Ws);
}

__global__ __launch_bounds__(256) void mlp2_kernel(
    const float* __restrict__ t, const float* __restrict__ W2,
    const float* __restrict__ b2, const float* __restrict__ h,
    float* __restrict__ outp) {
    __shared__ float As[16 * 68];
    __shared__ float Ws[16 * 68];
    gemm_body(t, W2, b2, h, nullptr, nullptr, outp, D_, H_, 2, As, Ws);
}

// ------- front: LN(slots) -> qk gemm (+bqk) and ct ------------------------
#define FRONT_SMEM ((64 * XS + 16 * 68) * 4)
__global__ __launch_bounds__(256) void front_kernel(
    const float* __restrict__ slots,
    const float* __restrict__ ln_g, const float* __restrict__ ln_b,
    const float* __restrict__ Wqk, const float* __restrict__ bqk,
    const float* __restrict__ us, const float* __restrict__ c0,
    float* __restrict__ qk, float* __restrict__ ct) {
    extern __shared__ float sm[];
    float* snS = sm;
    float* Ws  = sm + 64 * XS;
    int t = threadIdx.x, w = t >> 5, lane = t & 31;
    int r0 = blockIdx.y * 64, c0b = blockIdx.x * 64;

    const float4* g4 = (const float4*)ln_g;
    const float4* b4 = (const float4*)ln_b;
    float4 ga = g4[lane], gc = g4[lane + 32];
    float4 ba = b4[lane], bc = b4[lane + 32];
    for (int rr = 0; rr < 8; rr++) {
        int lr = w * 8 + rr;
        const float4* x4 = (const float4*)(slots + (size_t)(r0 + lr) * 256);
        float4 a = x4[lane], c = x4[lane + 32];
        float s  = a.x + a.y + a.z + a.w + c.x + c.y + c.z + c.w;
        float s2 = a.x*a.x + a.y*a.y + a.z*a.z + a.w*a.w
                 + c.x*c.x + c.y*c.y + c.z*c.z + c.w*c.w;
        #pragma unroll
        for (int o = 16; o; o >>= 1) {
            s  += __shfl_xor_sync(0xffffffffu, s,  o);
            s2 += __shfl_xor_sync(0xffffffffu, s2, o);
        }
        float mean = s * (1.0f / 256.0f);
        float var  = s2 * (1.0f / 256.0f) - mean * mean;
        float rstd = rsqrtf(var + EPS);
        float4 o1, o2;
        o1.x = (a.x - mean) * rstd * ga.x + ba.x;
        o1.y = (a.y - mean) * rstd * ga.y + ba.y;
        o1.z = (a.z - mean) * rstd * ga.z + ba.z;
        o1.w = (a.w - mean) * rstd * ga.w + ba.w;
        o2.x = (c.x - mean) * rstd * gc.x + bc.x;
        o2.y = (c.y - mean) * rstd * gc.y + bc.y;
        o2.z = (c.z - mean) * rstd * gc.z + bc.z;
        o2.w = (c.w - mean) * rstd * gc.w + bc.w;
        *(float4*)&snS[lr * XS + lane * 4] = o1;
        *(float4*)&snS[lr * XS + (lane + 32) * 4] = o2;
    }
    __syncthreads();

    if (blockIdx.x == 0 && t < 64) {
        float s = 0.0f;
        #pragma unroll 8
        for (int e = 0; e < 256; e++) s += snS[t * XS + e] * us[e];
        ct[r0 + t] = s + c0[0];
    }
    __syncthreads();

    int tx = t & 15, ty = t >> 4, lm = t >> 2, lk = (t & 3) * 4;
    u64 c2[4][2];
    #pragma unroll
    for (int i = 0; i < 4; i++) { c2[i][0] = 0ull; c2[i][1] = 0ull; }
    float4 wv = *(const float4*)&Wqk[(size_t)(c0b + lm) * 256 + lk];
    for (int k0 = 0; k0 < 256; k0 += 16) {
        Ws[(lk + 0) * 68 + lm] = wv.x; Ws[(lk + 1) * 68 + lm] = wv.y;
        Ws[(lk + 2) * 68 + lm] = wv.z; Ws[(lk + 3) * 68 + lm] = wv.w;
        __syncthreads();
        if (k0 + 16 < 256)
            wv = *(const float4*)&Wqk[(size_t)(c0b + lm) * 256 + k0 + 16 + lk];
        #pragma unroll
        for (int kk = 0; kk < 16; kk++) {
            ulonglong2 w2 = *(const ulonglong2*)&Ws[kk * 68 + tx * 4];
            #pragma unroll
            for (int i = 0; i < 4; i++) {
                float ai = snS[(ty * 4 + i) * XS + k0 + kk];
                u64 a2 = pack2(ai, ai);
                c2[i][0] = fma2(a2, w2.x, c2[i][0]);
                c2[i][1] = fma2(a2, w2.y, c2[i][1]);
            }
        }
        __syncthreads();
    }
    #pragma unroll
    for (int i = 0; i < 4; i++) {
        int r = r0 + ty * 4 + i;
        #pragma unroll
        for (int p = 0; p < 2; p++) {
            float v0, v1;
            unpack2(c2[i][p], v0, v1);
            int cc = c0b + tx * 4 + 2 * p;
            qk[(size_t)r * 256 + cc]     = v0 + bqk[cc];
            qk[(size_t)r * 256 + cc + 1] = v1 + bqk[cc + 1];
        }
    }
}

// --------- fused: LN(inputs) + logits + softmax + attn@x, 8 tiles/block ---
#define FUSED_SMEM ((64 * XS + 16 * 256 + 1024 + 1024 + 64 * AS + 16 + 32) * 4)

__global__ __launch_bounds__(256, 2) void fused_attn_kernel(
    const float* __restrict__ X,             // raw inputs [B,N,DIN]
    const float* __restrict__ lng, const float* __restrict__ lnb,
    const float* __restrict__ QK, const float* __restrict__ CT,
    float* __restrict__ part, float* __restrict__ rpart,
    float* __restrict__ attn_out) {
    extern __shared__ float sm[];
    float* xsm  = sm;                       // [64][XS]
    float* qsm  = sm + 64 * XS;             // [16][256]
    float* redA = qsm + 16 * 256;           // [16][64]
    float* redB = redA + 1024;              // [16][64]
    float* atsm = redB + 1024;              // [64][AS]
    float* csm  = atsm + 64 * AS;           // [16]
    float* wred = csm + 16;                 // [2][16]
    int b = blockIdx.y, grp = blockIdx.x;
    int tid = threadIdx.x;
    int w = tid >> 5, lane = tid & 31;

    // LN params per lane (column groups lane*4 and (lane+32)*4)
    const float4* g4 = (const float4*)lng;
    const float4* b4 = (const float4*)lnb;
    float4 ga = g4[lane], gc = g4[lane + 32];
    float4 ba = b4[lane], bc = b4[lane + 32];

    // per-block loads (q, ct) once for all 8 tiles
    for (int e = tid; e < S_ * 64; e += 256) {
        int s = e >> 6, c4 = (e & 63) * 4;
        *(float4*)&qsm[s * 256 + c4] =
            *(const float4*)&QK[((size_t)b * S_ + s) * DIN + c4];
    }
    if (tid < S_) csm[tid] = CT[b * S_ + tid];

    int n = tid & 63, dq = tid >> 6;
    int db = dq * 64;
    u64 uacc[8];
    #pragma unroll
    for (int sp = 0; sp < 8; sp++) uacc[sp] = 0ull;
    float rtot = 0.0f;

    for (int tl = 0; tl < GRP; tl++) {
        int tile = grp * GRP + tl;
        int n0 = tile * NB;
        const float* xb = X + ((size_t)b * N_ + n0) * DIN;
        __syncthreads();   // covers q/ct on tl==0, xsm/atsm reuse after
        for (int e = tid; e < 64 * 64; e += 256) {
            int row = e >> 6, c4 = (e & 63) * 4;
            *(float4*)&xsm[row * XS + c4] = *(const float4*)&xb[(size_t)row * DIN + c4];
        }
        __syncthreads();

        // ---- LayerNorm the 64 rows in place (warp w -> rows w*8..w*8+7) ----
        #pragma unroll
        for (int rr = 0; rr < 8; rr++) {
            float* xrow = xsm + (w * 8 + rr) * XS;
            float4 a = *(float4*)&xrow[lane * 4];
            float4 c = *(float4*)&xrow[(lane + 32) * 4];
            float s  = a.x + a.y + a.z + a.w + c.x + c.y + c.z + c.w;
            float s2 = a.x*a.x + a.y*a.y + a.z*a.z + a.w*a.w
                     + c.x*c.x + c.y*c.y + c.z*c.z + c.w*c.w;
            #pragma unroll
            for (int o = 16; o; o >>= 1) {
                s  += __shfl_xor_sync(0xffffffffu, s,  o);
                s2 += __shfl_xor_sync(0xffffffffu, s2, o);
            }
            float mean = s * (1.0f / 256.0f);
            float var  = s2 * (1.0f / 256.0f) - mean * mean;
            float rstd = rsqrtf(var + EPS);
            float4 o1, o2;
            o1.x = (a.x - mean) * rstd * ga.x + ba.x;
            o1.y = (a.y - mean) * rstd * ga.y + ba.y;
            o1.z = (a.z - mean) * rstd * ga.z + ba.z;
            o1.w = (a.w - mean) * rstd * ga.w + ba.w;
            o2.x = (c.x - mean) * rstd * gc.x + bc.x;
            o2.y = (c.y - mean) * rstd * gc.y + bc.y;
            o2.z = (c.z - mean) * rstd * gc.z + bc.z;
            o2.w = (c.w - mean) * rstd * gc.w + bc.w;
            *(float4*)&xrow[lane * 4] = o1;
            *(float4*)&xrow[(lane + 32) * 4] = o2;
        }
        __syncthreads();

        // ---- phase 1: logits[n][s], thread = (n = tid&63, dq = tid>>6) ----
        u64 acc[S_];
        #pragma unroll
        for (int s = 0; s < S_; s++) acc[s] = 0ull;
        const ulonglong2* xr = (const ulonglong2*)(xsm + n * XS + db);
        #pragma unroll 4
        for (int i = 0; i < 16; i++) {
            ulonglong2 xv = xr[i];
            const float* qb = qsm + db + i * 4;
            #pragma unroll
            for (int s = 0; s < S_; s++) {
                ulonglong2 qv = *(const ulonglong2*)(qb + s * 256);
                acc[s] = fma2(xv.x, qv.x, acc[s]);
                acc[s] = fma2(xv.y, qv.y, acc[s]);
            }
        }
        float p[S_];
        #pragma unroll
        for (int s = 0; s < S_; s++) p[s] = hsum2(acc[s]);

        if (dq == 2) {
            #pragma unroll
            for (int s = 0; s < S_; s++) redA[s * 64 + n] = p[s];
        }
        if (dq == 3) {
            #pragma unroll
            for (int s = 0; s < S_; s++) redB[s * 64 + n] = p[s];
        }
        __syncthreads();
        if (dq == 0) {
            #pragma unroll
            for (int s = 0; s < S_; s++) p[s] += redA[s * 64 + n];
        }
        if (dq == 1) {
            #pragma unroll
            for (int s = 0; s < S_; s++) {
                p[s] += redB[s * 64 + n];
                redB[s * 64 + n] = p[s];
            }
        }
        __syncthreads();

        // ---- softmax over s (threads 0..63, one per n) + rowsum ----
        if (tid < 64) {
            float mx = -1e30f;
            #pragma unroll
            for (int s = 0; s < S_; s++) {
                p[s] = p[s] + redB[s * 64 + n] + csm[s];
                mx = fmaxf(mx, p[s]);
            }
            float sum = 0.0f;
            #pragma unroll
            for (int s = 0; s < S_; s++) { p[s] = __expf(p[s] - mx); sum += p[s]; }
            float inv = 1.0f / sum;
            #pragma unroll
            for (int s = 0; s < S_; s++) {
                float a = p[s] * inv;
                p[s] = a;
                atsm[n * AS + s] = a;
                if (attn_out)
                    attn_out[((size_t)(b * S_ + s)) * N_ + n0 + n] = a;
            }
            #pragma unroll
            for (int s = 0; s < S_; s++) {
                float v = p[s];
                #pragma unroll
                for (int o = 16; o; o >>= 1) v += __shfl_xor_sync(0xffffffffu, v, o);
                if ((tid & 31) == 0) wred[(tid >> 5) * 16 + s] = v;
            }
        }
        __syncthreads();
        if (tid < S_) rtot += wred[tid] + wred[16 + tid];

        // ---- phase 3: accumulate uv over this tile's n ----
        #pragma unroll 4
        for (int nn = 0; nn < NB; nn++) {
            float xv = xsm[nn * XS + tid];
            u64 x2 = pack2(xv, xv);
            const ulonglong2* arow2 = (const ulonglong2*)(atsm + nn * AS);
            #pragma unroll
            for (int jj = 0; jj < 4; jj++) {
                ulonglong2 ap = arow2[jj];
                uacc[2 * jj]     = fma2(x2, ap.x, uacc[2 * jj]);
                uacc[2 * jj + 1] = fma2(x2, ap.y, uacc[2 * jj + 1]);
            }
        }
    }

    // one partial write per block
    float* po = part + ((size_t)(b * NGRP + grp) * S_) * DIN + tid;
    #pragma unroll
    for (int sp = 0; sp < 8; sp++) {
        float v0, v1;
        unpack2(uacc[sp], v0, v1);
        po[(size_t)(2 * sp) * DIN]     = v0;
        po[(size_t)(2 * sp + 1) * DIN] = v1;
    }
    if (tid < S_)
        rpart[((size_t)b * NGRP + grp) * S_ + tid] = rtot;
}

// ---------------- merged reductions (float4, 8-way) -----------------------
__global__ void reduce_kernel(const float* __restrict__ part,
                              const float* __restrict__ rpart,
                              float* __restrict__ uv,
                              float* __restrict__ r) {
    int idx4 = blockIdx.x * 256 + threadIdx.x;     // 0..32767
    int b = idx4 >> 10;
    int sd4 = (idx4 & 1023) * 4;
    const float* p = part + (size_t)b * NGRP * 4096 + sd4;
    float4 s = make_float4(0.f, 0.f, 0.f, 0.f);
    #pragma unroll
    for (int t = 0; t < NGRP; t++) {
        float4 v = *(const float4*)(p + (size_t)t * 4096);
        s.x += v.x; s.y += v.y; s.z += v.z; s.w += v.w;
    }
    *(float4*)&uv[(size_t)idx4 * 4] = s;
    if (blockIdx.x == 0) {
        for (int i = threadIdx.x; i < ROWS; i += 256) {
            const float* rp = rpart + (i >> 4) * NGRP * S_ + (i & 15);
            float v = 0.0f;
            #pragma unroll
            for (int t = 0; t < NGRP; t++) v += rp[t * S_];
            r[i] = v;
        }
    }
}

// ---------------- GRU + LN(m) fused (warp per row) ------------------------
__global__ void gru_ln_kernel(const float* __restrict__ gi,
                              const float* __restrict__ gh,
                              const float* __restrict__ slots,
                              const float* __restrict__ gg,
                              const float* __restrict__ bb,
                              float* __restrict__ h,
                              float* __restrict__ m) {
    int w = threadIdx.x >> 5, lane = threadIdx.x & 31;
    int row = blockIdx.x * 8 + w;
    const float* gir = gi + (size_t)row * 768;
    const float* ghr = gh + (size_t)row * 768;
    const float* hp  = slots + (size_t)row * 256;
    int c1 = lane * 4, c2i = c1 + 128;
    float hv[8];
    #pragma unroll
    for (int g = 0; g < 2; g++) {
        int c = g ? c2i : c1;
        float4 ir = *(const float4*)&gir[c];
        float4 hr = *(const float4*)&ghr[c];
        float4 iz = *(const float4*)&gir[c + 256];
        float4 hz = *(const float4*)&ghr[c + 256];
        float4 in = *(const float4*)&gir[c + 512];
        float4 hn = *(const float4*)&ghr[c + 512];
        float4 pv = *(const float4*)&hp[c];
        float rr, zz, nn;
        rr = sigmoidf(ir.x + hr.x); zz = sigmoidf(iz.x + hz.x);
        nn = tanhf(in.x + rr * hn.x); hv[g*4+0] = (1.0f - zz) * nn + zz * pv.x;
        rr = sigmoidf(ir.y + hr.y); zz = sigmoidf(iz.y + hz.y);
        nn = tanhf(in.y + rr * hn.y); hv[g*4+1] = (1.0f - zz) * nn + zz * pv.y;
        rr = sigmoidf(ir.z + hr.z); zz = sigmoidf(iz.z + hz.z);
        nn = tanhf(in.z + rr * hn.z); hv[g*4+2] = (1.0f - zz) * nn + zz * pv.z;
        rr = sigmoidf(ir.w + hr.w); zz = sigmoidf(iz.w + hz.w);
        nn = tanhf(in.w + rr * hn.w); hv[g*4+3] = (1.0f - zz) * nn + zz * pv.w;
    }
    float s = 0.0f, s2 = 0.0f;
    #pragma unroll
    for (int i = 0; i < 8; i++) { s += hv[i]; s2 += hv[i] * hv[i]; }
    #pragma unroll
    for (int o = 16; o; o >>= 1) {
        s  += __shfl_xor_sync(0xffffffffu, s,  o);
        s2 += __shfl_xor_sync(0xffffffffu, s2, o);
    }
    float mean = s * (1.0f / 256.0f);
    float var  = s2 * (1.0f / 256.0f) - mean * mean;
    float rstd = rsqrtf(var + EPS);
    float* hrow = h + (size_t)row * 256;
    float* mrow = m + (size_t)row * 256;
    #pragma unroll
    for (int g = 0; g < 2; g++) {
        int c = g ? c2i : c1;
        float4 gv = *(const float4*)&gg[c];
        float4 bv = *(const float4*)&bb[c];
        float4 hvv = make_float4(hv[g*4+0], hv[g*4+1], hv[g*4+2], hv[g*4+3]);
        float4 mv;
        mv.x = (hvv.x - mean) * rstd * gv.x + bv.x;
        mv.y = (hvv.y - mean) * rstd * gv.y + bv.y;
        mv.z = (hvv.z - mean) * rstd * gv.z + bv.z;
        mv.w = (hvv.w - mean) * rstd * gv.w + bv.w;
        *(float4*)&hrow[c] = hvv;
        *(float4*)&mrow[c] = mv;
    }
}

// ---------------- host side ------------------------------------------------
extern "C" void kernel_launch(void* const* d_in, const int* in_sizes, int n_in,
                              void* d_out, int out_size) {
    const float* inputs     = (const float*)d_in[0];
    const float* init_noise = (const float*)d_in[1];
    const float* slots_mu   = (const float*)d_in[2];
    const float* slots_sig  = (const float*)d_in[3];
    const float* ln_in_g    = (const float*)d_in[4];
    const float* ln_in_b    = (const float*)d_in[5];
    const float* ln_s_g     = (const float*)d_in[6];
    const float* ln_s_b     = (const float*)d_in[7];
    const float* ln_m_g     = (const float*)d_in[8];
    const float* ln_m_b     = (const float*)d_in[9];
    const float* Wk         = (const float*)d_in[10];
    const float* bk         = (const float*)d_in[11];
    const float* Wv         = (const float*)d_in[12];
    const float* bv         = (const float*)d_in[13];
    const float* Wq         = (const float*)d_in[14];
    const float* bq         = (const float*)d_in[15];
    const float* W_ih       = (const float*)d_in[16];
    const float* W_hh       = (const float*)d_in[17];
    const float* b_ih       = (const float*)d_in[18];
    const float* b_hh       = (const float*)d_in[19];
    const float* W1         = (const float*)d_in[20];
    const float* b1         = (const float*)d_in[21];
    const float* W2         = (const float*)d_in[22];
    const float* b2         = (const float*)d_in[23];
    float* out = (float*)d_out;

    float *slots, *qk, *ct, *uv, *r, *part, *rpart;
    float *gi, *gh, *h, *m, *t, *Wqk, *Wiv, *us, *bqk, *biv, *c0, *prec;
    cudaGetSymbolAddress((void**)&slots, g_slots);
    cudaGetSymbolAddress((void**)&qk,    g_qk);
    cudaGetSymbolAddress((void**)&ct,    g_ct);
    cudaGetSymbolAddress((void**)&uv,    g_uv);
    cudaGetSymbolAddress((void**)&r,     g_r);
    cudaGetSymbolAddress((void**)&part,  g_part);
    cudaGetSymbolAddress((void**)&rpart, g_rpart);
    cudaGetSymbolAddress((void**)&gi,    g_gi);
    cudaGetSymbolAddress((void**)&gh,    g_gh);
    cudaGetSymbolAddress((void**)&h,     g_h);
    cudaGetSymbolAddress((void**)&m,     g_m);
    cudaGetSymbolAddress((void**)&t,     g_t);
    cudaGetSymbolAddress((void**)&Wqk,   g_Wqk);
    cudaGetSymbolAddress((void**)&Wiv,   g_Wiv);
    cudaGetSymbolAddress((void**)&us,    g_us);
    cudaGetSymbolAddress((void**)&bqk,   g_bqk);
    cudaGetSymbolAddress((void**)&biv,   g_biv);
    cudaGetSymbolAddress((void**)&c0,    g_c0);
    cudaGetSymbolAddress((void**)&prec,  g_prec);

    cudaFuncSetAttribute(fused_attn_kernel,
                         cudaFuncAttributeMaxDynamicSharedMemorySize, FUSED_SMEM);
    cudaFuncSetAttribute(front_kernel,
                         cudaFuncAttributeMaxDynamicSharedMemorySize, FRONT_SMEM);

    const int BSD = ROWS * D_;      // 131072
    const int BSN = B_ * S_ * N_;   // 2097152

    // prologue
    slots_init_kernel<<<BSD / 256, 256>>>(init_noise, slots_mu, slots_sig, slots);
    prec_kernel<<<dim3(162, 4), 256>>>(Wk, Wq, W_ih, Wv, bk, bq, bv,
                                       prec, us, bqk, c0, biv);
    prec_reduce_kernel<<<256, 256>>>(prec, Wqk, Wiv);

    float* attn_out = out + (out_size - BSN);

    for (int it = 0; it < 3; it++) {
        front_kernel<<<dim3(DIN / 64, ROWS / 64), 256, FRONT_SMEM>>>(
            slots, ln_s_g, ln_s_b, Wqk, bqk, us, c0, qk, ct);
        fused_attn_kernel<<<dim3(NGRP, B_), 256, FUSED_SMEM>>>(
            inputs, ln_in_g, ln_in_b, qk, ct, part, rpart,
            (it == 2) ? attn_out : nullptr);
        reduce_kernel<<<(ROWS * DIN) / 1024, 256>>>(part, rpart, uv, r);
        gigh_kernel<<<dim3((3 * D_) / 64, ROWS / 64, 2), 256>>>(
            uv, slots, Wiv, W_hh, b_ih, b_hh, r, biv, gi, gh);
        gru_ln_kernel<<<ROWS / 8, 256>>>(gi, gh, slots, ln_m_g, ln_m_b, h, m);
        mlp1_kernel<<<dim3(H_ / 64, ROWS / 64), 256>>>(m, W1, b1, t);
        mlp2_kernel<<<dim3(D_ / 64, ROWS / 64), 256>>>(
            t, W2, b2, h, (it == 2) ? out : slots);
    }
}

// round 13
// speedup vs baseline: 1.1001x; 1.0321x over previous
#include <cuda_runtime.h>
#include <cstddef>
#include <cstdint>

#define B_  32
#define N_  4096
#define DIN 256
#define D_  256
#define S_  16
#define H_  512
#define EPS 1e-5f
#define SCALE 0.0625f
#define NB 64
#define GRP 8                // tiles per fused block
#define NGRP 8               // groups per batch
#define XS 260               // xsm row stride (floats)
#define AS 20                // atsm row stride
#define ROWS (B_*S_)         // 512

typedef unsigned long long u64;

__device__ __forceinline__ u64 fma2(u64 a, u64 b, u64 c) {
    u64 d;
    asm("fma.rn.f32x2 %0, %1, %2, %3;" : "=l"(d) : "l"(a), "l"(b), "l"(c));
    return d;
}
__device__ __forceinline__ u64 pack2(float lo, float hi) {
    u64 d;
    asm("mov.b64 %0, {%1, %2};" : "=l"(d) : "f"(lo), "f"(hi));
    return d;
}
__device__ __forceinline__ void unpack2(u64 v, float& lo, float& hi) {
    asm("mov.b64 {%0, %1}, %2;" : "=f"(lo), "=f"(hi) : "l"(v));
}
__device__ __forceinline__ float hsum2(u64 v) {
    float a, b; unpack2(v, a, b); return a + b;
}
__device__ __forceinline__ float sigmoidf(float x) { return 1.0f / (1.0f + __expf(-x)); }

// ---------------- scratch ----------------
__device__ float g_slots[ROWS * D_];
__device__ float g_qkp  [4 * ROWS * DIN];                 // split-k qk partials
__device__ float g_ct   [ROWS];
__device__ float g_uv   [ROWS * DIN];
__device__ float g_r    [ROWS];
__device__ float g_part [(size_t)B_ * NGRP * S_ * DIN];   // 2.1 MB
__device__ float g_rpart[B_ * NGRP * S_];
__device__ float g_gi   [ROWS * 3 * D_];
__device__ float g_gh   [ROWS * 3 * D_];
__device__ float g_h    [ROWS * D_];
__device__ float g_m    [ROWS * D_];
__device__ float g_t    [ROWS * H_];
__device__ float g_Wqk  [DIN * D_];
__device__ float g_Wiv  [3 * D_ * DIN];
__device__ float g_us   [D_];
__device__ float g_bqk  [DIN];
__device__ float g_biv  [3 * D_];
__device__ float g_c0   [1];
__device__ float g_prec [4 * 64 * 4096];

// ---------------- slots init ----------------
__global__ void slots_init_kernel(const float* __restrict__ noise,
                                  const float* __restrict__ mu,
                                  const float* __restrict__ sigma,
                                  float* __restrict__ slots) {
    int i = blockIdx.x * 256 + threadIdx.x;
    int d = i & (D_ - 1);
    slots[i] = mu[d] + sigma[d] * noise[i];
}

// ------------- combined split-k precompute + prep -------------------------
__global__ __launch_bounds__(256) void prec_kernel(
    const float* __restrict__ Wk, const float* __restrict__ Wq,
    const float* __restrict__ Wih, const float* __restrict__ Wv,
    const float* __restrict__ bk, const float* __restrict__ bq,
    const float* __restrict__ bv,
    float* __restrict__ partial,
    float* __restrict__ us, float* __restrict__ bqk,
    float* __restrict__ c0, float* __restrict__ biv) {
    int t = threadIdx.x;
    int tile = blockIdx.x, ks = blockIdx.y;

    if (tile >= 64) {
        if (ks != 0) return;
        int bx = tile - 64;
        if (bx < 96) {
            int warp = t >> 5, lane = t & 31;
            int r = bx * 8 + warp;
            float s = 0.0f;
            #pragma unroll
            for (int e = lane; e < D_; e += 32) s += Wih[(size_t)r * D_ + e] * bv[e];
            #pragma unroll
            for (int o = 16; o; o >>= 1) s += __shfl_xor_sync(0xffffffffu, s, o);
            if (lane == 0) biv[r] = s;
        } else if (bx == 96) {
            float s = 0.0f;
            for (int e = 0; e < D_; e++) s += bk[e] * Wq[(size_t)e * D_ + t];
            us[t] = SCALE * s;
            if (t == 0) {
                float c = 0.0f;
                for (int e = 0; e < D_; e++) c += bk[e] * bq[e];
                *c0 = SCALE * c;
            }
        } else {
            float s = 0.0f;
            for (int e = 0; e < D_; e++) s += bq[e] * Wk[(size_t)e * DIN + t];
            bqk[t] = SCALE * s;
        }
        return;
    }

    __shared__ float As[16][68];
    __shared__ float Bs[16][68];
    bool ta = (tile < 16);
    int t2 = ta ? tile : tile - 16;
    int m0 = (t2 >> 2) * 64, n0 = (t2 & 3) * 64;
    const float* A  = ta ? Wk : Wih;
    const float* Bm = ta ? Wq : Wv;
    int kbase = ks * 64;
    int tx = t & 15, ty = t >> 4;
    int mB = t & 63, kkb = t >> 6;
    int lm = t >> 2, lk = (t & 3) * 4;

    u64 c2[4][2];
    #pragma unroll
    for (int i = 0; i < 4; i++) { c2[i][0] = 0ull; c2[i][1] = 0ull; }

    float ar[4], br[4];
    float4 av;
    if (ta) {
        #pragma unroll
        for (int i = 0; i < 4; i++)
            ar[i] = A[(size_t)(kbase + kkb + 4 * i) * 256 + m0 + mB];
    } else {
        av = *(const float4*)&A[(size_t)(m0 + lm) * 256 + kbase + lk];
    }
    #pragma unroll
    for (int i = 0; i < 4; i++)
        br[i] = Bm[(size_t)(kbase + kkb + 4 * i) * 256 + n0 + mB];

    for (int ki = 0; ki < 4; ki++) {
        if (ta) {
            #pragma unroll
            for (int i = 0; i < 4; i++) As[kkb + 4 * i][mB] = ar[i];
        } else {
            As[lk + 0][lm] = av.x; As[lk + 1][lm] = av.y;
            As[lk + 2][lm] = av.z; As[lk + 3][lm] = av.w;
        }
        #pragma unroll
        for (int i = 0; i < 4; i++) Bs[kkb + 4 * i][mB] = br[i];
        __syncthreads();
        if (ki < 3) {
            int knext = kbase + (ki + 1) * 16;
            if (ta) {
                #pragma unroll
                for (int i = 0; i < 4; i++)
                    ar[i] = A[(size_t)(knext + kkb + 4 * i) * 256 + m0 + mB];
            } else {
                av = *(const float4*)&A[(size_t)(m0 + lm) * 256 + knext + lk];
            }
            #pragma unroll
            for (int i = 0; i < 4; i++)
                br[i] = Bm[(size_t)(knext + kkb + 4 * i) * 256 + n0 + mB];
        }
        #pragma unroll
        for (int kk = 0; kk < 16; kk++) {
            ulonglong2 w2 = *(const ulonglong2*)&Bs[kk][tx * 4];
            #pragma unroll
            for (int i = 0; i < 4; i++) {
                float ai = As[kk][ty * 4 + i];
                u64 a2 = pack2(ai, ai);
                c2[i][0] = fma2(a2, w2.x, c2[i][0]);
                c2[i][1] = fma2(a2, w2.y, c2[i][1]);
            }
        }
        __syncthreads();
    }

    size_t base = ((size_t)(ks * 64 + tile)) * 4096;
    #pragma unroll
    for (int i = 0; i < 4; i++) {
        #pragma unroll
        for (int p = 0; p < 2; p++) {
            float v0, v1;
            unpack2(c2[i][p], v0, v1);
            int off = (ty * 4 + i) * 64 + tx * 4 + 2 * p;
            partial[base + off]     = v0;
            partial[base + off + 1] = v1;
        }
    }
}

__global__ void prec_reduce_kernel(const float* __restrict__ partial,
                                   float* __restrict__ Wqk,
                                   float* __restrict__ Wiv) {
    int idx4 = blockIdx.x * 256 + threadIdx.x;
    int tile = idx4 >> 10;
    int w4 = (idx4 & 1023) * 4;
    const float* p = partial + (size_t)tile * 4096 + w4;
    float4 s = *(const float4*)p;
    #pragma unroll
    for (int ks = 1; ks < 4; ks++) {
        float4 v = *(const float4*)(p + (size_t)ks * 64 * 4096);
        s.x += v.x; s.y += v.y; s.z += v.z; s.w += v.w;
    }
    int i = w4 >> 6, j = w4 & 63;
    if (tile < 16) {
        int m = (tile >> 2) * 64 + i, n = (tile & 3) * 64 + j;
        s.x *= SCALE; s.y *= SCALE; s.z *= SCALE; s.w *= SCALE;
        *(float4*)&Wqk[(size_t)m * 256 + n] = s;
    } else {
        int t2 = tile - 16;
        int m = (t2 >> 2) * 64 + i, n = (t2 & 3) * 64 + j;
        *(float4*)&Wiv[(size_t)m * 256 + n] = s;
    }
}

// ---- shared gemm body ----------------------------------------------------
__device__ __forceinline__ void gemm_body(
    const float* __restrict__ A, const float* __restrict__ W,
    const float* __restrict__ bias, const float* __restrict__ extraM,
    const float* __restrict__ rvec, const float* __restrict__ cvec,
    float* __restrict__ C, int Nn, int K, int mode,
    float* As, float* Ws) {
    int t = threadIdx.x, tx = t & 15, ty = t >> 4;
    int m0 = blockIdx.y * 64, n0 = blockIdx.x * 64;
    int lm = t >> 2, lk = (t & 3) * 4;
    u64 c2[4][2];
    #pragma unroll
    for (int i = 0; i < 4; i++) { c2[i][0] = 0ull; c2[i][1] = 0ull; }

    float4 av = *(const float4*)&A[(size_t)(m0 + lm) * K + lk];
    float4 wv = *(const float4*)&W[(size_t)(n0 + lm) * K + lk];

    for (int k0 = 0; k0 < K; k0 += 16) {
        As[(lk + 0) * 68 + lm] = av.x; As[(lk + 1) * 68 + lm] = av.y;
        As[(lk + 2) * 68 + lm] = av.z; As[(lk + 3) * 68 + lm] = av.w;
        Ws[(lk + 0) * 68 + lm] = wv.x; Ws[(lk + 1) * 68 + lm] = wv.y;
        Ws[(lk + 2) * 68 + lm] = wv.z; Ws[(lk + 3) * 68 + lm] = wv.w;
        __syncthreads();
        if (k0 + 16 < K) {
            av = *(const float4*)&A[(size_t)(m0 + lm) * K + k0 + 16 + lk];
            wv = *(const float4*)&W[(size_t)(n0 + lm) * K + k0 + 16 + lk];
        }
        #pragma unroll
        for (int kk = 0; kk < 16; kk++) {
            float4 a = *(const float4*)&As[kk * 68 + ty * 4];
            ulonglong2 w2 = *(const ulonglong2*)&Ws[kk * 68 + tx * 4];
            float arr[4] = {a.x, a.y, a.z, a.w};
            #pragma unroll
            for (int i = 0; i < 4; i++) {
                u64 a2 = pack2(arr[i], arr[i]);
                c2[i][0] = fma2(a2, w2.x, c2[i][0]);
                c2[i][1] = fma2(a2, w2.y, c2[i][1]);
            }
        }
        __syncthreads();
    }
    #pragma unroll
    for (int i = 0; i < 4; i++) {
        int r = m0 + ty * 4 + i;
        #pragma unroll
        for (int p = 0; p < 2; p++) {
            float v0, v1;
            unpack2(c2[i][p], v0, v1);
            int c0c = n0 + tx * 4 + 2 * p;
            v0 += bias[c0c]; v1 += bias[c0c + 1];
            if (mode == 1) { v0 = fmaxf(v0, 0.0f); v1 = fmaxf(v1, 0.0f); }
            if (mode == 2) {
                v0 += extraM[(size_t)r * Nn + c0c];
                v1 += extraM[(size_t)r * Nn + c0c + 1];
            }
            if (mode == 3) {
                float rv = rvec[r];
                v0 += rv * cvec[c0c]; v1 += rv * cvec[c0c + 1];
            }
            C[(size_t)r * Nn + c0c]     = v0;
            C[(size_t)r * Nn + c0c + 1] = v1;
        }
    }
}

__global__ __launch_bounds__(256) void gigh_kernel(
    const float* __restrict__ uv, const float* __restrict__ slots,
    const float* __restrict__ Wiv, const float* __restrict__ Whh,
    const float* __restrict__ bih, const float* __restrict__ bhh,
    const float* __restrict__ r, const float* __restrict__ biv,
    float* __restrict__ gi, float* __restrict__ gh) {
    __shared__ float As[16 * 68];
    __shared__ float Ws[16 * 68];
    if (blockIdx.z == 0)
        gemm_body(uv, Wiv, bih, nullptr, r, biv, gi, 3 * D_, DIN, 3, As, Ws);
    else
        gemm_body(slots, Whh, bhh, nullptr, nullptr, nullptr, gh, 3 * D_, D_, 0, As, Ws);
}

__global__ __launch_bounds__(256) void mlp1_kernel(
    const float* __restrict__ m, const float* __restrict__ W1,
    const float* __restrict__ b1, float* __restrict__ t) {
    __shared__ float As[16 * 68];
    __shared__ float Ws[16 * 68];
    gemm_body(m, W1, b1, nullptr, nullptr, nullptr, t, H_, D_, 1, As, Ws);
}

__global__ __launch_bounds__(256) void mlp2_kernel(
    const float* __restrict__ t, const float* __restrict__ W2,
    const float* __restrict__ b2, const float* __restrict__ h,
    float* __restrict__ outp) {
    __shared__ float As[16 * 68];
    __shared__ float Ws[16 * 68];
    gemm_body(t, W2, b2, h, nullptr, nullptr, outp, D_, H_, 2, As, Ws);
}

// ------- front: LN(slots) -> split-k qk partials and ct -------------------
// grid (4, 8, 4): x = 64-col tile, y = 64-row tile, z = k-chunk (64)
#define FRONT_SMEM ((64 * XS + 16 * 68) * 4)
__global__ __launch_bounds__(256) void front_kernel(
    const float* __restrict__ slots,
    const float* __restrict__ ln_g, const float* __restrict__ ln_b,
    const float* __restrict__ Wqk,
    const float* __restrict__ us, const float* __restrict__ c0,
    float* __restrict__ qkp, float* __restrict__ ct) {
    extern __shared__ float sm[];
    float* snS = sm;
    float* Ws  = sm + 64 * XS;
    int t = threadIdx.x, w = t >> 5, lane = t & 31;
    int r0 = blockIdx.y * 64, c0b = blockIdx.x * 64;
    int ks = blockIdx.z, kbase = ks * 64;

    const float4* g4 = (const float4*)ln_g;
    const float4* b4 = (const float4*)ln_b;
    float4 ga = g4[lane], gc = g4[lane + 32];
    float4 ba = b4[lane], bc = b4[lane + 32];
    for (int rr = 0; rr < 8; rr++) {
        int lr = w * 8 + rr;
        const float4* x4 = (const float4*)(slots + (size_t)(r0 + lr) * 256);
        float4 a = x4[lane], c = x4[lane + 32];
        float s  = a.x + a.y + a.z + a.w + c.x + c.y + c.z + c.w;
        float s2 = a.x*a.x + a.y*a.y + a.z*a.z + a.w*a.w
                 + c.x*c.x + c.y*c.y + c.z*c.z + c.w*c.w;
        #pragma unroll
        for (int o = 16; o; o >>= 1) {
            s  += __shfl_xor_sync(0xffffffffu, s,  o);
            s2 += __shfl_xor_sync(0xffffffffu, s2, o);
        }
        float mean = s * (1.0f / 256.0f);
        float var  = s2 * (1.0f / 256.0f) - mean * mean;
        float rstd = rsqrtf(var + EPS);
        float4 o1, o2;
        o1.x = (a.x - mean) * rstd * ga.x + ba.x;
        o1.y = (a.y - mean) * rstd * ga.y + ba.y;
        o1.z = (a.z - mean) * rstd * ga.z + ba.z;
        o1.w = (a.w - mean) * rstd * ga.w + ba.w;
        o2.x = (c.x - mean) * rstd * gc.x + bc.x;
        o2.y = (c.y - mean) * rstd * gc.y + bc.y;
        o2.z = (c.z - mean) * rstd * gc.z + bc.z;
        o2.w = (c.w - mean) * rstd * gc.w + bc.w;
        *(float4*)&snS[lr * XS + lane * 4] = o1;
        *(float4*)&snS[lr * XS + (lane + 32) * 4] = o2;
    }
    __syncthreads();

    if (blockIdx.x == 0 && ks == 0 && t < 64) {
        float s = 0.0f;
        #pragma unroll 8
        for (int e = 0; e < 256; e++) s += snS[t * XS + e] * us[e];
        ct[r0 + t] = s + c0[0];
    }
    __syncthreads();

    // qk partial: sum over k in [kbase, kbase+64)
    int tx = t & 15, ty = t >> 4, lm = t >> 2, lk = (t & 3) * 4;
    u64 c2[4][2];
    #pragma unroll
    for (int i = 0; i < 4; i++) { c2[i][0] = 0ull; c2[i][1] = 0ull; }
    float4 wv = *(const float4*)&Wqk[(size_t)(c0b + lm) * 256 + kbase + lk];
    #pragma unroll
    for (int kc = 0; kc < 4; kc++) {
        int k0 = kbase + kc * 16;
        Ws[(lk + 0) * 68 + lm] = wv.x; Ws[(lk + 1) * 68 + lm] = wv.y;
        Ws[(lk + 2) * 68 + lm] = wv.z; Ws[(lk + 3) * 68 + lm] = wv.w;
        __syncthreads();
        if (kc < 3)
            wv = *(const float4*)&Wqk[(size_t)(c0b + lm) * 256 + k0 + 16 + lk];
        #pragma unroll
        for (int kk = 0; kk < 16; kk++) {
            ulonglong2 w2 = *(const ulonglong2*)&Ws[kk * 68 + tx * 4];
            #pragma unroll
            for (int i = 0; i < 4; i++) {
                float ai = snS[(ty * 4 + i) * XS + k0 + kk];
                u64 a2 = pack2(ai, ai);
                c2[i][0] = fma2(a2, w2.x, c2[i][0]);
                c2[i][1] = fma2(a2, w2.y, c2[i][1]);
            }
        }
        __syncthreads();
    }
    float* qo = qkp + (size_t)ks * ROWS * 256;
    #pragma unroll
    for (int i = 0; i < 4; i++) {
        int r = r0 + ty * 4 + i;
        #pragma unroll
        for (int p = 0; p < 2; p++) {
            float v0, v1;
            unpack2(c2[i][p], v0, v1);
            int cc = c0b + tx * 4 + 2 * p;
            qo[(size_t)r * 256 + cc]     = v0;
            qo[(size_t)r * 256 + cc + 1] = v1;
        }
    }
}

// --------- fused: LN(inputs) + logits + softmax + attn@x, 8 tiles/block ---
#define FUSED_SMEM ((64 * XS + 16 * 256 + 1024 + 1024 + 64 * AS + 16 + 32) * 4)

__global__ __launch_bounds__(256, 2) void fused_attn_kernel(
    const float* __restrict__ X,             // raw inputs [B,N,DIN]
    const float* __restrict__ lng, const float* __restrict__ lnb,
    const float* __restrict__ QKP, const float* __restrict__ bqk,
    const float* __restrict__ CT,
    float* __restrict__ part, float* __restrict__ rpart,
    float* __restrict__ attn_out) {
    extern __shared__ float sm[];
    float* xsm  = sm;                       // [64][XS]
    float* qsm  = sm + 64 * XS;             // [16][256]
    float* redA = qsm + 16 * 256;           // [16][64]
    float* redB = redA + 1024;              // [16][64]
    float* atsm = redB + 1024;              // [64][AS]
    float* csm  = atsm + 64 * AS;           // [16]
    float* wred = csm + 16;                 // [2][16]
    int b = blockIdx.y, grp = blockIdx.x;
    int tid = threadIdx.x;
    int w = tid >> 5, lane = tid & 31;

    const float4* g4 = (const float4*)lng;
    const float4* b4 = (const float4*)lnb;
    float4 ga = g4[lane], gc = g4[lane + 32];
    float4 ba = b4[lane], bc = b4[lane + 32];

    // per-block loads: qsm = sum of 4 qk partials + bqk; ct
    for (int e = tid; e < S_ * 64; e += 256) {
        int s = e >> 6, c4 = (e & 63) * 4;
        size_t off = ((size_t)b * S_ + s) * 256 + c4;
        float4 q0 = *(const float4*)&QKP[off];
        float4 q1 = *(const float4*)&QKP[(size_t)ROWS * 256 + off];
        float4 q2 = *(const float4*)&QKP[(size_t)2 * ROWS * 256 + off];
        float4 q3 = *(const float4*)&QKP[(size_t)3 * ROWS * 256 + off];
        float4 bb4 = *(const float4*)&bqk[c4];
        float4 qv;
        qv.x = q0.x + q1.x + q2.x + q3.x + bb4.x;
        qv.y = q0.y + q1.y + q2.y + q3.y + bb4.y;
        qv.z = q0.z + q1.z + q2.z + q3.z + bb4.z;
        qv.w = q0.w + q1.w + q2.w + q3.w + bb4.w;
        *(float4*)&qsm[s * 256 + c4] = qv;
    }
    if (tid < S_) csm[tid] = CT[b * S_ + tid];

    int n = tid & 63, dq = tid >> 6;
    int db = dq * 64;
    u64 uacc[8];
    #pragma unroll
    for (int sp = 0; sp < 8; sp++) uacc[sp] = 0ull;
    float rtot = 0.0f;

    for (int tl = 0; tl < GRP; tl++) {
        int tile = grp * GRP + tl;
        int n0 = tile * NB;
        const float* xb = X + ((size_t)b * N_ + n0) * DIN;
        __syncthreads();   // covers q/ct on tl==0, xsm/atsm reuse after
        for (int e = tid; e < 64 * 64; e += 256) {
            int row = e >> 6, c4 = (e & 63) * 4;
            *(float4*)&xsm[row * XS + c4] = *(const float4*)&xb[(size_t)row * DIN + c4];
        }
        __syncthreads();

        // ---- LayerNorm the 64 rows in place ----
        #pragma unroll
        for (int rr = 0; rr < 8; rr++) {
            float* xrow = xsm + (w * 8 + rr) * XS;
            float4 a = *(float4*)&xrow[lane * 4];
            float4 c = *(float4*)&xrow[(lane + 32) * 4];
            float s  = a.x + a.y + a.z + a.w + c.x + c.y + c.z + c.w;
            float s2 = a.x*a.x + a.y*a.y + a.z*a.z + a.w*a.w
                     + c.x*c.x + c.y*c.y + c.z*c.z + c.w*c.w;
            #pragma unroll
            for (int o = 16; o; o >>= 1) {
                s  += __shfl_xor_sync(0xffffffffu, s,  o);
                s2 += __shfl_xor_sync(0xffffffffu, s2, o);
            }
            float mean = s * (1.0f / 256.0f);
            float var  = s2 * (1.0f / 256.0f) - mean * mean;
            float rstd = rsqrtf(var + EPS);
            float4 o1, o2;
            o1.x = (a.x - mean) * rstd * ga.x + ba.x;
            o1.y = (a.y - mean) * rstd * ga.y + ba.y;
            o1.z = (a.z - mean) * rstd * ga.z + ba.z;
            o1.w = (a.w - mean) * rstd * ga.w + ba.w;
            o2.x = (c.x - mean) * rstd * gc.x + bc.x;
            o2.y = (c.y - mean) * rstd * gc.y + bc.y;
            o2.z = (c.z - mean) * rstd * gc.z + bc.z;
            o2.w = (c.w - mean) * rstd * gc.w + bc.w;
            *(float4*)&xrow[lane * 4] = o1;
            *(float4*)&xrow[(lane + 32) * 4] = o2;
        }
        __syncthreads();

        // ---- phase 1: logits[n][s] ----
        u64 acc[S_];
        #pragma unroll
        for (int s = 0; s < S_; s++) acc[s] = 0ull;
        const ulonglong2* xr = (const ulonglong2*)(xsm + n * XS + db);
        #pragma unroll 4
        for (int i = 0; i < 16; i++) {
            ulonglong2 xv = xr[i];
            const float* qb = qsm + db + i * 4;
            #pragma unroll
            for (int s = 0; s < S_; s++) {
                ulonglong2 qv = *(const ulonglong2*)(qb + s * 256);
                acc[s] = fma2(xv.x, qv.x, acc[s]);
                acc[s] = fma2(xv.y, qv.y, acc[s]);
            }
        }
        float p[S_];
        #pragma unroll
        for (int s = 0; s < S_; s++) p[s] = hsum2(acc[s]);

        if (dq == 2) {
            #pragma unroll
            for (int s = 0; s < S_; s++) redA[s * 64 + n] = p[s];
        }
        if (dq == 3) {
            #pragma unroll
            for (int s = 0; s < S_; s++) redB[s * 64 + n] = p[s];
        }
        __syncthreads();
        if (dq == 0) {
            #pragma unroll
            for (int s = 0; s < S_; s++) p[s] += redA[s * 64 + n];
        }
        if (dq == 1) {
            #pragma unroll
            for (int s = 0; s < S_; s++) {
                p[s] += redB[s * 64 + n];
                redB[s * 64 + n] = p[s];
            }
        }
        __syncthreads();

        // ---- softmax over s + rowsum ----
        if (tid < 64) {
            float mx = -1e30f;
            #pragma unroll
            for (int s = 0; s < S_; s++) {
                p[s] = p[s] + redB[s * 64 + n] + csm[s];
                mx = fmaxf(mx, p[s]);
            }
            float sum = 0.0f;
            #pragma unroll
            for (int s = 0; s < S_; s++) { p[s] = __expf(p[s] - mx); sum += p[s]; }
            float inv = 1.0f / sum;
            #pragma unroll
            for (int s = 0; s < S_; s++) {
                float a = p[s] * inv;
                p[s] = a;
                atsm[n * AS + s] = a;
                if (attn_out)
                    attn_out[((size_t)(b * S_ + s)) * N_ + n0 + n] = a;
            }
            #pragma unroll
            for (int s = 0; s < S_; s++) {
                float v = p[s];
                #pragma unroll
                for (int o = 16; o; o >>= 1) v += __shfl_xor_sync(0xffffffffu, v, o);
                if ((tid & 31) == 0) wred[(tid >> 5) * 16 + s] = v;
            }
        }
        __syncthreads();
        if (tid < S_) rtot += wred[tid] + wred[16 + tid];

        // ---- phase 3: accumulate uv ----
        #pragma unroll 4
        for (int nn = 0; nn < NB; nn++) {
            float xv = xsm[nn * XS + tid];
            u64 x2 = pack2(xv, xv);
            const ulonglong2* arow2 = (const ulonglong2*)(atsm + nn * AS);
            #pragma unroll
            for (int jj = 0; jj < 4; jj++) {
                ulonglong2 ap = arow2[jj];
                uacc[2 * jj]     = fma2(x2, ap.x, uacc[2 * jj]);
                uacc[2 * jj + 1] = fma2(x2, ap.y, uacc[2 * jj + 1]);
            }
        }
    }

    float* po = part + ((size_t)(b * NGRP + grp) * S_) * DIN + tid;
    #pragma unroll
    for (int sp = 0; sp < 8; sp++) {
        float v0, v1;
        unpack2(uacc[sp], v0, v1);
        po[(size_t)(2 * sp) * DIN]     = v0;
        po[(size_t)(2 * sp + 1) * DIN] = v1;
    }
    if (tid < S_)
        rpart[((size_t)b * NGRP + grp) * S_ + tid] = rtot;
}

// ---------------- merged reductions (float4, 8-way) -----------------------
__global__ void reduce_kernel(const float* __restrict__ part,
                              const float* __restrict__ rpart,
                              float* __restrict__ uv,
                              float* __restrict__ r) {
    int idx4 = blockIdx.x * 256 + threadIdx.x;     // 0..32767
    int b = idx4 >> 10;
    int sd4 = (idx4 & 1023) * 4;
    const float* p = part + (size_t)b * NGRP * 4096 + sd4;
    float4 s = make_float4(0.f, 0.f, 0.f, 0.f);
    #pragma unroll
    for (int t = 0; t < NGRP; t++) {
        float4 v = *(const float4*)(p + (size_t)t * 4096);
        s.x += v.x; s.y += v.y; s.z += v.z; s.w += v.w;
    }
    *(float4*)&uv[(size_t)idx4 * 4] = s;
    if (blockIdx.x == 0) {
        for (int i = threadIdx.x; i < ROWS; i += 256) {
            const float* rp = rpart + (i >> 4) * NGRP * S_ + (i & 15);
            float v = 0.0f;
            #pragma unroll
            for (int t = 0; t < NGRP; t++) v += rp[t * S_];
            r[i] = v;
        }
    }
}

// ---------------- GRU + LN(m) fused (warp per row) ------------------------
__global__ void gru_ln_kernel(const float* __restrict__ gi,
                              const float* __restrict__ gh,
                              const float* __restrict__ slots,
                              const float* __restrict__ gg,
                              const float* __restrict__ bb,
                              float* __restrict__ h,
                              float* __restrict__ m) {
    int w = threadIdx.x >> 5, lane = threadIdx.x & 31;
    int row = blockIdx.x * 8 + w;
    const float* gir = gi + (size_t)row * 768;
    const float* ghr = gh + (size_t)row * 768;
    const float* hp  = slots + (size_t)row * 256;
    int c1 = lane * 4, c2i = c1 + 128;
    float hv[8];
    #pragma unroll
    for (int g = 0; g < 2; g++) {
        int c = g ? c2i : c1;
        float4 ir = *(const float4*)&gir[c];
        float4 hr = *(const float4*)&ghr[c];
        float4 iz = *(const float4*)&gir[c + 256];
        float4 hz = *(const float4*)&ghr[c + 256];
        float4 in = *(const float4*)&gir[c + 512];
        float4 hn = *(const float4*)&ghr[c + 512];
        float4 pv = *(const float4*)&hp[c];
        float rr, zz, nn;
        rr = sigmoidf(ir.x + hr.x); zz = sigmoidf(iz.x + hz.x);
        nn = tanhf(in.x + rr * hn.x); hv[g*4+0] = (1.0f - zz) * nn + zz * pv.x;
        rr = sigmoidf(ir.y + hr.y); zz = sigmoidf(iz.y + hz.y);
        nn = tanhf(in.y + rr * hn.y); hv[g*4+1] = (1.0f - zz) * nn + zz * pv.y;
        rr = sigmoidf(ir.z + hr.z); zz = sigmoidf(iz.z + hz.z);
        nn = tanhf(in.z + rr * hn.z); hv[g*4+2] = (1.0f - zz) * nn + zz * pv.z;
        rr = sigmoidf(ir.w + hr.w); zz = sigmoidf(iz.w + hz.w);
        nn = tanhf(in.w + rr * hn.w); hv[g*4+3] = (1.0f - zz) * nn + zz * pv.w;
    }
    float s = 0.0f, s2 = 0.0f;
    #pragma unroll
    for (int i = 0; i < 8; i++) { s += hv[i]; s2 += hv[i] * hv[i]; }
    #pragma unroll
    for (int o = 16; o; o >>= 1) {
        s  += __shfl_xor_sync(0xffffffffu, s,  o);
        s2 += __shfl_xor_sync(0xffffffffu, s2, o);
    }
    float mean = s * (1.0f / 256.0f);
    float var  = s2 * (1.0f / 256.0f) - mean * mean;
    float rstd = rsqrtf(var + EPS);
    float* hrow = h + (size_t)row * 256;
    float* mrow = m + (size_t)row * 256;
    #pragma unroll
    for (int g = 0; g < 2; g++) {
        int c = g ? c2i : c1;
        float4 gv = *(const float4*)&gg[c];
        float4 bv = *(const float4*)&bb[c];
        float4 hvv = make_float4(hv[g*4+0], hv[g*4+1], hv[g*4+2], hv[g*4+3]);
        float4 mv;
        mv.x = (hvv.x - mean) * rstd * gv.x + bv.x;
        mv.y = (hvv.y - mean) * rstd * gv.y + bv.y;
        mv.z = (hvv.z - mean) * rstd * gv.z + bv.z;
        mv.w = (hvv.w - mean) * rstd * gv.w + bv.w;
        *(float4*)&hrow[c] = hvv;
        *(float4*)&mrow[c] = mv;
    }
}

// ---------------- host side ------------------------------------------------
extern "C" void kernel_launch(void* const* d_in, const int* in_sizes, int n_in,
                              void* d_out, int out_size) {
    const float* inputs     = (const float*)d_in[0];
    const float* init_noise = (const float*)d_in[1];
    const float* slots_mu   = (const float*)d_in[2];
    const float* slots_sig  = (const float*)d_in[3];
    const float* ln_in_g    = (const float*)d_in[4];
    const float* ln_in_b    = (const float*)d_in[5];
    const float* ln_s_g     = (const float*)d_in[6];
    const float* ln_s_b     = (const float*)d_in[7];
    const float* ln_m_g     = (const float*)d_in[8];
    const float* ln_m_b     = (const float*)d_in[9];
    const float* Wk         = (const float*)d_in[10];
    const float* bk         = (const float*)d_in[11];
    const float* Wv         = (const float*)d_in[12];
    const float* bv         = (const float*)d_in[13];
    const float* Wq         = (const float*)d_in[14];
    const float* bq         = (const float*)d_in[15];
    const float* W_ih       = (const float*)d_in[16];
    const float* W_hh       = (const float*)d_in[17];
    const float* b_ih       = (const float*)d_in[18];
    const float* b_hh       = (const float*)d_in[19];
    const float* W1         = (const float*)d_in[20];
    const float* b1         = (const float*)d_in[21];
    const float* W2         = (const float*)d_in[22];
    const float* b2         = (const float*)d_in[23];
    float* out = (float*)d_out;

    float *slots, *qkp, *ct, *uv, *r, *part, *rpart;
    float *gi, *gh, *h, *m, *t, *Wqk, *Wiv, *us, *bqk, *biv, *c0, *prec;
    cudaGetSymbolAddress((void**)&slots, g_slots);
    cudaGetSymbolAddress((void**)&qkp,   g_qkp);
    cudaGetSymbolAddress((void**)&ct,    g_ct);
    cudaGetSymbolAddress((void**)&uv,    g_uv);
    cudaGetSymbolAddress((void**)&r,     g_r);
    cudaGetSymbolAddress((void**)&part,  g_part);
    cudaGetSymbolAddress((void**)&rpart, g_rpart);
    cudaGetSymbolAddress((void**)&gi,    g_gi);
    cudaGetSymbolAddress((void**)&gh,    g_gh);
    cudaGetSymbolAddress((void**)&h,     g_h);
    cudaGetSymbolAddress((void**)&m,     g_m);
    cudaGetSymbolAddress((void**)&t,     g_t);
    cudaGetSymbolAddress((void**)&Wqk,   g_Wqk);
    cudaGetSymbolAddress((void**)&Wiv,   g_Wiv);
    cudaGetSymbolAddress((void**)&us,    g_us);
    cudaGetSymbolAddress((void**)&bqk,   g_bqk);
    cudaGetSymbolAddress((void**)&biv,   g_biv);
    cudaGetSymbolAddress((void**)&c0,    g_c0);
    cudaGetSymbolAddress((void**)&prec,  g_prec);

    cudaFuncSetAttribute(fused_attn_kernel,
                         cudaFuncAttributeMaxDynamicSharedMemorySize, FUSED_SMEM);
    cudaFuncSetAttribute(front_kernel,
                         cudaFuncAttributeMaxDynamicSharedMemorySize, FRONT_SMEM);

    const int BSD = ROWS * D_;      // 131072
    const int BSN = B_ * S_ * N_;   // 2097152

    // prologue
    slots_init_kernel<<<BSD / 256, 256>>>(init_noise, slots_mu, slots_sig, slots);
    prec_kernel<<<dim3(162, 4), 256>>>(Wk, Wq, W_ih, Wv, bk, bq, bv,
                                       prec, us, bqk, c0, biv);
    prec_reduce_kernel<<<256, 256>>>(prec, Wqk, Wiv);

    float* attn_out = out + (out_size - BSN);

    for (int it = 0; it < 3; it++) {
        front_kernel<<<dim3(DIN / 64, ROWS / 64, 4), 256, FRONT_SMEM>>>(
            slots, ln_s_g, ln_s_b, Wqk, us, c0, qkp, ct);
        fused_attn_kernel<<<dim3(NGRP, B_), 256, FUSED_SMEM>>>(
            inputs, ln_in_g, ln_in_b, qkp, bqk, ct, part, rpart,
            (it == 2) ? attn_out : nullptr);
        reduce_kernel<<<(ROWS * DIN) / 1024, 256>>>(part, rpart, uv, r);
        gigh_kernel<<<dim3((3 * D_) / 64, ROWS / 64, 2), 256>>>(
            uv, slots, Wiv, W_hh, b_ih, b_hh, r, biv, gi, gh);
        gru_ln_kernel<<<ROWS / 8, 256>>>(gi, gh, slots, ln_m_g, ln_m_b, h, m);
        mlp1_kernel<<<dim3(H_ / 64, ROWS / 64), 256>>>(m, W1, b1, t);
        mlp2_kernel<<<dim3(D_ / 64, ROWS / 64), 256>>>(
            t, W2, b2, h, (it == 2) ? out : slots);
    }
}

// round 14
// speedup vs baseline: 1.1116x; 1.0105x over previous
#include <cuda_runtime.h>
#include <cstddef>
#include <cstdint>

#define B_  32
#define N_  4096
#define DIN 256
#define D_  256
#define S_  16
#define H_  512
#define EPS 1e-5f
#define SCALE 0.0625f
#define NB 64
#define GRP 8                // tiles per fused block
#define NGRP 8               // groups per batch
#define XS 260               // xsm row stride (floats)
#define AS 20                // atsm row stride
#define ROWS (B_*S_)         // 512

typedef unsigned long long u64;

__device__ __forceinline__ u64 fma2(u64 a, u64 b, u64 c) {
    u64 d;
    asm("fma.rn.f32x2 %0, %1, %2, %3;" : "=l"(d) : "l"(a), "l"(b), "l"(c));
    return d;
}
__device__ __forceinline__ u64 pack2(float lo, float hi) {
    u64 d;
    asm("mov.b64 %0, {%1, %2};" : "=l"(d) : "f"(lo), "f"(hi));
    return d;
}
__device__ __forceinline__ void unpack2(u64 v, float& lo, float& hi) {
    asm("mov.b64 {%0, %1}, %2;" : "=f"(lo), "=f"(hi) : "l"(v));
}
__device__ __forceinline__ float hsum2(u64 v) {
    float a, b; unpack2(v, a, b); return a + b;
}
__device__ __forceinline__ float sigmoidf(float x) { return 1.0f / (1.0f + __expf(-x)); }

// ---------------- scratch ----------------
__device__ float g_slots[ROWS * D_];
__device__ float g_qkp  [4 * ROWS * DIN];                 // split-k qk partials
__device__ float g_ct   [ROWS];
__device__ float g_uv   [ROWS * DIN];
__device__ float g_r    [ROWS];
__device__ float g_part [(size_t)B_ * NGRP * S_ * DIN];   // 2.1 MB
__device__ float g_rpart[B_ * NGRP * S_];
__device__ float g_gi   [ROWS * 3 * D_];
__device__ float g_gh   [ROWS * 3 * D_];
__device__ float g_h    [ROWS * D_];
__device__ float g_m    [ROWS * D_];
__device__ float g_t    [ROWS * H_];
__device__ float g_Wqk  [DIN * D_];
__device__ float g_Wiv  [3 * D_ * DIN];
__device__ float g_us   [D_];
__device__ float g_bqk  [DIN];
__device__ float g_biv  [3 * D_];
__device__ float g_c0   [1];
__device__ float g_prec [4 * 64 * 4096];

// ---------------- slots init ----------------
__global__ void slots_init_kernel(const float* __restrict__ noise,
                                  const float* __restrict__ mu,
                                  const float* __restrict__ sigma,
                                  float* __restrict__ slots) {
    int i = blockIdx.x * 256 + threadIdx.x;
    int d = i & (D_ - 1);
    slots[i] = mu[d] + sigma[d] * noise[i];
}

// ------------- combined split-k precompute + prep -------------------------
__global__ __launch_bounds__(256) void prec_kernel(
    const float* __restrict__ Wk, const float* __restrict__ Wq,
    const float* __restrict__ Wih, const float* __restrict__ Wv,
    const float* __restrict__ bk, const float* __restrict__ bq,
    const float* __restrict__ bv,
    float* __restrict__ partial,
    float* __restrict__ us, float* __restrict__ bqk,
    float* __restrict__ c0, float* __restrict__ biv) {
    int t = threadIdx.x;
    int tile = blockIdx.x, ks = blockIdx.y;

    if (tile >= 64) {
        if (ks != 0) return;
        int bx = tile - 64;
        if (bx < 96) {
            int warp = t >> 5, lane = t & 31;
            int r = bx * 8 + warp;
            float s = 0.0f;
            #pragma unroll
            for (int e = lane; e < D_; e += 32) s += Wih[(size_t)r * D_ + e] * bv[e];
            #pragma unroll
            for (int o = 16; o; o >>= 1) s += __shfl_xor_sync(0xffffffffu, s, o);
            if (lane == 0) biv[r] = s;
        } else if (bx == 96) {
            float s = 0.0f;
            for (int e = 0; e < D_; e++) s += bk[e] * Wq[(size_t)e * D_ + t];
            us[t] = SCALE * s;
            if (t == 0) {
                float c = 0.0f;
                for (int e = 0; e < D_; e++) c += bk[e] * bq[e];
                *c0 = SCALE * c;
            }
        } else {
            float s = 0.0f;
            for (int e = 0; e < D_; e++) s += bq[e] * Wk[(size_t)e * DIN + t];
            bqk[t] = SCALE * s;
        }
        return;
    }

    __shared__ float As[16][68];
    __shared__ float Bs[16][68];
    bool ta = (tile < 16);
    int t2 = ta ? tile : tile - 16;
    int m0 = (t2 >> 2) * 64, n0 = (t2 & 3) * 64;
    const float* A  = ta ? Wk : Wih;
    const float* Bm = ta ? Wq : Wv;
    int kbase = ks * 64;
    int tx = t & 15, ty = t >> 4;
    int mB = t & 63, kkb = t >> 6;
    int lm = t >> 2, lk = (t & 3) * 4;

    u64 c2[4][2];
    #pragma unroll
    for (int i = 0; i < 4; i++) { c2[i][0] = 0ull; c2[i][1] = 0ull; }

    float ar[4], br[4];
    float4 av;
    if (ta) {
        #pragma unroll
        for (int i = 0; i < 4; i++)
            ar[i] = A[(size_t)(kbase + kkb + 4 * i) * 256 + m0 + mB];
    } else {
        av = *(const float4*)&A[(size_t)(m0 + lm) * 256 + kbase + lk];
    }
    #pragma unroll
    for (int i = 0; i < 4; i++)
        br[i] = Bm[(size_t)(kbase + kkb + 4 * i) * 256 + n0 + mB];

    for (int ki = 0; ki < 4; ki++) {
        if (ta) {
            #pragma unroll
            for (int i = 0; i < 4; i++) As[kkb + 4 * i][mB] = ar[i];
        } else {
            As[lk + 0][lm] = av.x; As[lk + 1][lm] = av.y;
            As[lk + 2][lm] = av.z; As[lk + 3][lm] = av.w;
        }
        #pragma unroll
        for (int i = 0; i < 4; i++) Bs[kkb + 4 * i][mB] = br[i];
        __syncthreads();
        if (ki < 3) {
            int knext = kbase + (ki + 1) * 16;
            if (ta) {
                #pragma unroll
                for (int i = 0; i < 4; i++)
                    ar[i] = A[(size_t)(knext + kkb + 4 * i) * 256 + m0 + mB];
            } else {
                av = *(const float4*)&A[(size_t)(m0 + lm) * 256 + knext + lk];
            }
            #pragma unroll
            for (int i = 0; i < 4; i++)
                br[i] = Bm[(size_t)(knext + kkb + 4 * i) * 256 + n0 + mB];
        }
        #pragma unroll
        for (int kk = 0; kk < 16; kk++) {
            ulonglong2 w2 = *(const ulonglong2*)&Bs[kk][tx * 4];
            #pragma unroll
            for (int i = 0; i < 4; i++) {
                float ai = As[kk][ty * 4 + i];
                u64 a2 = pack2(ai, ai);
                c2[i][0] = fma2(a2, w2.x, c2[i][0]);
                c2[i][1] = fma2(a2, w2.y, c2[i][1]);
            }
        }
        __syncthreads();
    }

    size_t base = ((size_t)(ks * 64 + tile)) * 4096;
    #pragma unroll
    for (int i = 0; i < 4; i++) {
        #pragma unroll
        for (int p = 0; p < 2; p++) {
            float v0, v1;
            unpack2(c2[i][p], v0, v1);
            int off = (ty * 4 + i) * 64 + tx * 4 + 2 * p;
            partial[base + off]     = v0;
            partial[base + off + 1] = v1;
        }
    }
}

__global__ void prec_reduce_kernel(const float* __restrict__ partial,
                                   float* __restrict__ Wqk,
                                   float* __restrict__ Wiv) {
    int idx4 = blockIdx.x * 256 + threadIdx.x;
    int tile = idx4 >> 10;
    int w4 = (idx4 & 1023) * 4;
    const float* p = partial + (size_t)tile * 4096 + w4;
    float4 s = *(const float4*)p;
    #pragma unroll
    for (int ks = 1; ks < 4; ks++) {
        float4 v = *(const float4*)(p + (size_t)ks * 64 * 4096);
        s.x += v.x; s.y += v.y; s.z += v.z; s.w += v.w;
    }
    int i = w4 >> 6, j = w4 & 63;
    if (tile < 16) {
        int m = (tile >> 2) * 64 + i, n = (tile & 3) * 64 + j;
        s.x *= SCALE; s.y *= SCALE; s.z *= SCALE; s.w *= SCALE;
        *(float4*)&Wqk[(size_t)m * 256 + n] = s;
    } else {
        int t2 = tile - 16;
        int m = (t2 >> 2) * 64 + i, n = (t2 & 3) * 64 + j;
        *(float4*)&Wiv[(size_t)m * 256 + n] = s;
    }
}

// ---- shared gemm body ----------------------------------------------------
__device__ __forceinline__ void gemm_body(
    const float* __restrict__ A, const float* __restrict__ W,
    const float* __restrict__ bias, const float* __restrict__ extraM,
    const float* __restrict__ rvec, const float* __restrict__ cvec,
    float* __restrict__ C, int Nn, int K, int mode,
    float* As, float* Ws) {
    int t = threadIdx.x, tx = t & 15, ty = t >> 4;
    int m0 = blockIdx.y * 64, n0 = blockIdx.x * 64;
    int lm = t >> 2, lk = (t & 3) * 4;
    u64 c2[4][2];
    #pragma unroll
    for (int i = 0; i < 4; i++) { c2[i][0] = 0ull; c2[i][1] = 0ull; }

    float4 av = *(const float4*)&A[(size_t)(m0 + lm) * K + lk];
    float4 wv = *(const float4*)&W[(size_t)(n0 + lm) * K + lk];

    for (int k0 = 0; k0 < K; k0 += 16) {
        As[(lk + 0) * 68 + lm] = av.x; As[(lk + 1) * 68 + lm] = av.y;
        As[(lk + 2) * 68 + lm] = av.z; As[(lk + 3) * 68 + lm] = av.w;
        Ws[(lk + 0) * 68 + lm] = wv.x; Ws[(lk + 1) * 68 + lm] = wv.y;
        Ws[(lk + 2) * 68 + lm] = wv.z; Ws[(lk + 3) * 68 + lm] = wv.w;
        __syncthreads();
        if (k0 + 16 < K) {
            av = *(const float4*)&A[(size_t)(m0 + lm) * K + k0 + 16 + lk];
            wv = *(const float4*)&W[(size_t)(n0 + lm) * K + k0 + 16 + lk];
        }
        #pragma unroll
        for (int kk = 0; kk < 16; kk++) {
            float4 a = *(const float4*)&As[kk * 68 + ty * 4];
            ulonglong2 w2 = *(const ulonglong2*)&Ws[kk * 68 + tx * 4];
            float arr[4] = {a.x, a.y, a.z, a.w};
            #pragma unroll
            for (int i = 0; i < 4; i++) {
                u64 a2 = pack2(arr[i], arr[i]);
                c2[i][0] = fma2(a2, w2.x, c2[i][0]);
                c2[i][1] = fma2(a2, w2.y, c2[i][1]);
            }
        }
        __syncthreads();
    }
    #pragma unroll
    for (int i = 0; i < 4; i++) {
        int r = m0 + ty * 4 + i;
        #pragma unroll
        for (int p = 0; p < 2; p++) {
            float v0, v1;
            unpack2(c2[i][p], v0, v1);
            int c0c = n0 + tx * 4 + 2 * p;
            v0 += bias[c0c]; v1 += bias[c0c + 1];
            if (mode == 1) { v0 = fmaxf(v0, 0.0f); v1 = fmaxf(v1, 0.0f); }
            if (mode == 2) {
                v0 += extraM[(size_t)r * Nn + c0c];
                v1 += extraM[(size_t)r * Nn + c0c + 1];
            }
            if (mode == 3) {
                float rv = rvec[r];
                v0 += rv * cvec[c0c]; v1 += rv * cvec[c0c + 1];
            }
            C[(size_t)r * Nn + c0c]     = v0;
            C[(size_t)r * Nn + c0c + 1] = v1;
        }
    }
}

__global__ __launch_bounds__(256) void gigh_kernel(
    const float* __restrict__ uv, const float* __restrict__ slots,
    const float* __restrict__ Wiv, const float* __restrict__ Whh,
    const float* __restrict__ bih, const float* __restrict__ bhh,
    const float* __restrict__ r, const float* __restrict__ biv,
    float* __restrict__ gi, float* __restrict__ gh) {
    __shared__ float As[16 * 68];
    __shared__ float Ws[16 * 68];
    if (blockIdx.z == 0)
        gemm_body(uv, Wiv, bih, nullptr, r, biv, gi, 3 * D_, DIN, 3, As, Ws);
    else
        gemm_body(slots, Whh, bhh, nullptr, nullptr, nullptr, gh, 3 * D_, D_, 0, As, Ws);
}

__global__ __launch_bounds__(256) void mlp1_kernel(
    const float* __restrict__ m, const float* __restrict__ W1,
    const float* __restrict__ b1, float* __restrict__ t) {
    __shared__ float As[16 * 68];
    __shared__ float Ws[16 * 68];
    gemm_body(m, W1, b1, nullptr, nullptr, nullptr, t, H_, D_, 1, As, Ws);
}

__global__ __launch_bounds__(256) void mlp2_kernel(
    const float* __restrict__ t, const float* __restrict__ W2,
    const float* __restrict__ b2, const float* __restrict__ h,
    float* __restrict__ outp) {
    __shared__ float As[16 * 68];
    __shared__ float Ws[16 * 68];
    gemm_body(t, W2, b2, h, nullptr, nullptr, outp, D_, H_, 2, As, Ws);
}

// ------- front: LN(slots) -> split-k qk partials and ct -------------------
// grid (4, 8, 4): x = 64-col tile, y = 64-row tile, z = k-chunk (64)
#define FRONT_SMEM ((64 * XS + 16 * 68) * 4)
__global__ __launch_bounds__(256) void front_kernel(
    const float* __restrict__ slots,
    const float* __restrict__ ln_g, const float* __restrict__ ln_b,
    const float* __restrict__ Wqk,
    const float* __restrict__ us, const float* __restrict__ c0,
    float* __restrict__ qkp, float* __restrict__ ct) {
    extern __shared__ float sm[];
    float* snS = sm;
    float* Ws  = sm + 64 * XS;
    int t = threadIdx.x, w = t >> 5, lane = t & 31;
    int r0 = blockIdx.y * 64, c0b = blockIdx.x * 64;
    int ks = blockIdx.z, kbase = ks * 64;

    const float4* g4 = (const float4*)ln_g;
    const float4* b4 = (const float4*)ln_b;
    float4 ga = g4[lane], gc = g4[lane + 32];
    float4 ba = b4[lane], bc = b4[lane + 32];

    // LN with batched prefetch: two batches of 4 rows (8 LDG.128 in flight)
    #pragma unroll
    for (int bt = 0; bt < 2; bt++) {
        float4 ar[4], cr[4];
        #pragma unroll
        for (int rr = 0; rr < 4; rr++) {
            int lr = w * 8 + bt * 4 + rr;
            const float4* x4 = (const float4*)(slots + (size_t)(r0 + lr) * 256);
            ar[rr] = x4[lane];
            cr[rr] = x4[lane + 32];
        }
        #pragma unroll
        for (int rr = 0; rr < 4; rr++) {
            int lr = w * 8 + bt * 4 + rr;
            float4 a = ar[rr], c = cr[rr];
            float s  = a.x + a.y + a.z + a.w + c.x + c.y + c.z + c.w;
            float s2 = a.x*a.x + a.y*a.y + a.z*a.z + a.w*a.w
                     + c.x*c.x + c.y*c.y + c.z*c.z + c.w*c.w;
            #pragma unroll
            for (int o = 16; o; o >>= 1) {
                s  += __shfl_xor_sync(0xffffffffu, s,  o);
                s2 += __shfl_xor_sync(0xffffffffu, s2, o);
            }
            float mean = s * (1.0f / 256.0f);
            float var  = s2 * (1.0f / 256.0f) - mean * mean;
            float rstd = rsqrtf(var + EPS);
            float4 o1, o2;
            o1.x = (a.x - mean) * rstd * ga.x + ba.x;
            o1.y = (a.y - mean) * rstd * ga.y + ba.y;
            o1.z = (a.z - mean) * rstd * ga.z + ba.z;
            o1.w = (a.w - mean) * rstd * ga.w + ba.w;
            o2.x = (c.x - mean) * rstd * gc.x + bc.x;
            o2.y = (c.y - mean) * rstd * gc.y + bc.y;
            o2.z = (c.z - mean) * rstd * gc.z + bc.z;
            o2.w = (c.w - mean) * rstd * gc.w + bc.w;
            *(float4*)&snS[lr * XS + lane * 4] = o1;
            *(float4*)&snS[lr * XS + (lane + 32) * 4] = o2;
        }
    }
    __syncthreads();

    if (blockIdx.x == 0 && ks == 0 && t < 64) {
        float s = 0.0f;
        #pragma unroll 8
        for (int e = 0; e < 256; e++) s += snS[t * XS + e] * us[e];
        ct[r0 + t] = s + c0[0];
    }
    __syncthreads();

    // qk partial: sum over k in [kbase, kbase+64)
    int tx = t & 15, ty = t >> 4, lm = t >> 2, lk = (t & 3) * 4;
    u64 c2[4][2];
    #pragma unroll
    for (int i = 0; i < 4; i++) { c2[i][0] = 0ull; c2[i][1] = 0ull; }
    float4 wv = *(const float4*)&Wqk[(size_t)(c0b + lm) * 256 + kbase + lk];
    #pragma unroll
    for (int kc = 0; kc < 4; kc++) {
        int k0 = kbase + kc * 16;
        Ws[(lk + 0) * 68 + lm] = wv.x; Ws[(lk + 1) * 68 + lm] = wv.y;
        Ws[(lk + 2) * 68 + lm] = wv.z; Ws[(lk + 3) * 68 + lm] = wv.w;
        __syncthreads();
        if (kc < 3)
            wv = *(const float4*)&Wqk[(size_t)(c0b + lm) * 256 + k0 + 16 + lk];
        #pragma unroll
        for (int kk = 0; kk < 16; kk++) {
            ulonglong2 w2 = *(const ulonglong2*)&Ws[kk * 68 + tx * 4];
            #pragma unroll
            for (int i = 0; i < 4; i++) {
                float ai = snS[(ty * 4 + i) * XS + k0 + kk];
                u64 a2 = pack2(ai, ai);
                c2[i][0] = fma2(a2, w2.x, c2[i][0]);
                c2[i][1] = fma2(a2, w2.y, c2[i][1]);
            }
        }
        __syncthreads();
    }
    float* qo = qkp + (size_t)ks * ROWS * 256;
    #pragma unroll
    for (int i = 0; i < 4; i++) {
        int r = r0 + ty * 4 + i;
        #pragma unroll
        for (int p = 0; p < 2; p++) {
            float v0, v1;
            unpack2(c2[i][p], v0, v1);
            int cc = c0b + tx * 4 + 2 * p;
            qo[(size_t)r * 256 + cc]     = v0;
            qo[(size_t)r * 256 + cc + 1] = v1;
        }
    }
}

// --------- fused: LN(inputs) + logits + softmax + attn@x, 8 tiles/block ---
#define FUSED_SMEM ((64 * XS + 16 * 256 + 1024 + 1024 + 64 * AS + 16 + 32) * 4)

__global__ __launch_bounds__(256, 2) void fused_attn_kernel(
    const float* __restrict__ X,             // raw inputs [B,N,DIN]
    const float* __restrict__ lng, const float* __restrict__ lnb,
    const float* __restrict__ QKP, const float* __restrict__ bqk,
    const float* __restrict__ CT,
    float* __restrict__ part, float* __restrict__ rpart,
    float* __restrict__ attn_out) {
    extern __shared__ float sm[];
    float* xsm  = sm;                       // [64][XS]
    float* qsm  = sm + 64 * XS;             // [16][256]
    float* redA = qsm + 16 * 256;           // [16][64]
    float* redB = redA + 1024;              // [16][64]
    float* atsm = redB + 1024;              // [64][AS]
    float* csm  = atsm + 64 * AS;           // [16]
    float* wred = csm + 16;                 // [2][16]
    int b = blockIdx.y, grp = blockIdx.x;
    int tid = threadIdx.x;
    int w = tid >> 5, lane = tid & 31;

    const float4* g4 = (const float4*)lng;
    const float4* b4 = (const float4*)lnb;
    float4 ga = g4[lane], gc = g4[lane + 32];
    float4 ba = b4[lane], bc = b4[lane + 32];

    // per-block loads: qsm = sum of 4 qk partials + bqk; ct
    for (int e = tid; e < S_ * 64; e += 256) {
        int s = e >> 6, c4 = (e & 63) * 4;
        size_t off = ((size_t)b * S_ + s) * 256 + c4;
        float4 q0 = *(const float4*)&QKP[off];
        float4 q1 = *(const float4*)&QKP[(size_t)ROWS * 256 + off];
        float4 q2 = *(const float4*)&QKP[(size_t)2 * ROWS * 256 + off];
        float4 q3 = *(const float4*)&QKP[(size_t)3 * ROWS * 256 + off];
        float4 bb4 = *(const float4*)&bqk[c4];
        float4 qv;
        qv.x = q0.x + q1.x + q2.x + q3.x + bb4.x;
        qv.y = q0.y + q1.y + q2.y + q3.y + bb4.y;
        qv.z = q0.z + q1.z + q2.z + q3.z + bb4.z;
        qv.w = q0.w + q1.w + q2.w + q3.w + bb4.w;
        *(float4*)&qsm[s * 256 + c4] = qv;
    }
    if (tid < S_) csm[tid] = CT[b * S_ + tid];

    int n = tid & 63, dq = tid >> 6;
    int db = dq * 64;
    u64 uacc[8];
    #pragma unroll
    for (int sp = 0; sp < 8; sp++) uacc[sp] = 0ull;
    float rtot = 0.0f;

    for (int tl = 0; tl < GRP; tl++) {
        int tile = grp * GRP + tl;
        int n0 = tile * NB;
        const float* xb = X + ((size_t)b * N_ + n0) * DIN;
        __syncthreads();   // covers q/ct on tl==0, xsm/atsm reuse after
        for (int e = tid; e < 64 * 64; e += 256) {
            int row = e >> 6, c4 = (e & 63) * 4;
            *(float4*)&xsm[row * XS + c4] = *(const float4*)&xb[(size_t)row * DIN + c4];
        }
        __syncthreads();

        // ---- LayerNorm the 64 rows in place ----
        #pragma unroll
        for (int rr = 0; rr < 8; rr++) {
            float* xrow = xsm + (w * 8 + rr) * XS;
            float4 a = *(float4*)&xrow[lane * 4];
            float4 c = *(float4*)&xrow[(lane + 32) * 4];
            float s  = a.x + a.y + a.z + a.w + c.x + c.y + c.z + c.w;
            float s2 = a.x*a.x + a.y*a.y + a.z*a.z + a.w*a.w
                     + c.x*c.x + c.y*c.y + c.z*c.z + c.w*c.w;
            #pragma unroll
            for (int o = 16; o; o >>= 1) {
                s  += __shfl_xor_sync(0xffffffffu, s,  o);
                s2 += __shfl_xor_sync(0xffffffffu, s2, o);
            }
            float mean = s * (1.0f / 256.0f);
            float var  = s2 * (1.0f / 256.0f) - mean * mean;
            float rstd = rsqrtf(var + EPS);
            float4 o1, o2;
            o1.x = (a.x - mean) * rstd * ga.x + ba.x;
            o1.y = (a.y - mean) * rstd * ga.y + ba.y;
            o1.z = (a.z - mean) * rstd * ga.z + ba.z;
            o1.w = (a.w - mean) * rstd * ga.w + ba.w;
            o2.x = (c.x - mean) * rstd * gc.x + bc.x;
            o2.y = (c.y - mean) * rstd * gc.y + bc.y;
            o2.z = (c.z - mean) * rstd * gc.z + bc.z;
            o2.w = (c.w - mean) * rstd * gc.w + bc.w;
            *(float4*)&xrow[lane * 4] = o1;
            *(float4*)&xrow[(lane + 32) * 4] = o2;
        }
        __syncthreads();

        // ---- phase 1: logits[n][s] ----
        u64 acc[S_];
        #pragma unroll
        for (int s = 0; s < S_; s++) acc[s] = 0ull;
        const ulonglong2* xr = (const ulonglong2*)(xsm + n * XS + db);
        #pragma unroll 4
        for (int i = 0; i < 16; i++) {
            ulonglong2 xv = xr[i];
            const float* qb = qsm + db + i * 4;
            #pragma unroll
            for (int s = 0; s < S_; s++) {
                ulonglong2 qv = *(const ulonglong2*)(qb + s * 256);
                acc[s] = fma2(xv.x, qv.x, acc[s]);
                acc[s] = fma2(xv.y, qv.y, acc[s]);
            }
        }
        float p[S_];
        #pragma unroll
        for (int s = 0; s < S_; s++) p[s] = hsum2(acc[s]);

        if (dq == 2) {
            #pragma unroll
            for (int s = 0; s < S_; s++) redA[s * 64 + n] = p[s];
        }
        if (dq == 3) {
            #pragma unroll
            for (int s = 0; s < S_; s++) redB[s * 64 + n] = p[s];
        }
        __syncthreads();
        if (dq == 0) {
            #pragma unroll
            for (int s = 0; s < S_; s++) p[s] += redA[s * 64 + n];
        }
        if (dq == 1) {
            #pragma unroll
            for (int s = 0; s < S_; s++) {
                p[s] += redB[s * 64 + n];
                redB[s * 64 + n] = p[s];
            }
        }
        __syncthreads();

        // ---- softmax over s + rowsum ----
        if (tid < 64) {
            float mx = -1e30f;
            #pragma unroll
            for (int s = 0; s < S_; s++) {
                p[s] = p[s] + redB[s * 64 + n] + csm[s];
                mx = fmaxf(mx, p[s]);
            }
            float sum = 0.0f;
            #pragma unroll
            for (int s = 0; s < S_; s++) { p[s] = __expf(p[s] - mx); sum += p[s]; }
            float inv = 1.0f / sum;
            #pragma unroll
            for (int s = 0; s < S_; s++) {
                float a = p[s] * inv;
                p[s] = a;
                atsm[n * AS + s] = a;
                if (attn_out)
                    attn_out[((size_t)(b * S_ + s)) * N_ + n0 + n] = a;
            }
            #pragma unroll
            for (int s = 0; s < S_; s++) {
                float v = p[s];
                #pragma unroll
                for (int o = 16; o; o >>= 1) v += __shfl_xor_sync(0xffffffffu, v, o);
                if ((tid & 31) == 0) wred[(tid >> 5) * 16 + s] = v;
            }
        }
        __syncthreads();
        if (tid < S_) rtot += wred[tid] + wred[16 + tid];

        // ---- phase 3: accumulate uv ----
        #pragma unroll 4
        for (int nn = 0; nn < NB; nn++) {
            float xv = xsm[nn * XS + tid];
            u64 x2 = pack2(xv, xv);
            const ulonglong2* arow2 = (const ulonglong2*)(atsm + nn * AS);
            #pragma unroll
            for (int jj = 0; jj < 4; jj++) {
                ulonglong2 ap = arow2[jj];
                uacc[2 * jj]     = fma2(x2, ap.x, uacc[2 * jj]);
                uacc[2 * jj + 1] = fma2(x2, ap.y, uacc[2 * jj + 1]);
            }
        }
    }

    float* po = part + ((size_t)(b * NGRP + grp) * S_) * DIN + tid;
    #pragma unroll
    for (int sp = 0; sp < 8; sp++) {
        float v0, v1;
        unpack2(uacc[sp], v0, v1);
        po[(size_t)(2 * sp) * DIN]     = v0;
        po[(size_t)(2 * sp + 1) * DIN] = v1;
    }
    if (tid < S_)
        rpart[((size_t)b * NGRP + grp) * S_ + tid] = rtot;
}

// ---------------- merged reductions (float4, 8-way) -----------------------
__global__ void reduce_kernel(const float* __restrict__ part,
                              const float* __restrict__ rpart,
                              float* __restrict__ uv,
                              float* __restrict__ r) {
    int idx4 = blockIdx.x * 256 + threadIdx.x;     // 0..32767
    int b = idx4 >> 10;
    int sd4 = (idx4 & 1023) * 4;
    const float* p = part + (size_t)b * NGRP * 4096 + sd4;
    float4 s = make_float4(0.f, 0.f, 0.f, 0.f);
    #pragma unroll
    for (int t = 0; t < NGRP; t++) {
        float4 v = *(const float4*)(p + (size_t)t * 4096);
        s.x += v.x; s.y += v.y; s.z += v.z; s.w += v.w;
    }
    *(float4*)&uv[(size_t)idx4 * 4] = s;
    if (blockIdx.x == 0) {
        for (int i = threadIdx.x; i < ROWS; i += 256) {
            const float* rp = rpart + (i >> 4) * NGRP * S_ + (i & 15);
            float v = 0.0f;
            #pragma unroll
            for (int t = 0; t < NGRP; t++) v += rp[t * S_];
            r[i] = v;
        }
    }
}

// ---------------- GRU + LN(m) fused (warp per row) ------------------------
__global__ void gru_ln_kernel(const float* __restrict__ gi,
                              const float* __restrict__ gh,
                              const float* __restrict__ slots,
                              const float* __restrict__ gg,
                              const float* __restrict__ bb,
                              float* __restrict__ h,
                              float* __restrict__ m) {
    int w = threadIdx.x >> 5, lane = threadIdx.x & 31;
    int row = blockIdx.x * 8 + w;
    const float* gir = gi + (size_t)row * 768;
    const float* ghr = gh + (size_t)row * 768;
    const float* hp  = slots + (size_t)row * 256;
    int c1 = lane * 4, c2i = c1 + 128;
    float hv[8];
    #pragma unroll
    for (int g = 0; g < 2; g++) {
        int c = g ? c2i : c1;
        float4 ir = *(const float4*)&gir[c];
        float4 hr = *(const float4*)&ghr[c];
        float4 iz = *(const float4*)&gir[c + 256];
        float4 hz = *(const float4*)&ghr[c + 256];
        float4 in = *(const float4*)&gir[c + 512];
        float4 hn = *(const float4*)&ghr[c + 512];
        float4 pv = *(const float4*)&hp[c];
        float rr, zz, nn;
        rr = sigmoidf(ir.x + hr.x); zz = sigmoidf(iz.x + hz.x);
        nn = tanhf(in.x + rr * hn.x); hv[g*4+0] = (1.0f - zz) * nn + zz * pv.x;
        rr = sigmoidf(ir.y + hr.y); zz = sigmoidf(iz.y + hz.y);
        nn = tanhf(in.y + rr * hn.y); hv[g*4+1] = (1.0f - zz) * nn + zz * pv.y;
        rr = sigmoidf(ir.z + hr.z); zz = sigmoidf(iz.z + hz.z);
        nn = tanhf(in.z + rr * hn.z); hv[g*4+2] = (1.0f - zz) * nn + zz * pv.z;
        rr = sigmoidf(ir.w + hr.w); zz = sigmoidf(iz.w + hz.w);
        nn = tanhf(in.w + rr * hn.w); hv[g*4+3] = (1.0f - zz) * nn + zz * pv.w;
    }
    float s = 0.0f, s2 = 0.0f;
    #pragma unroll
    for (int i = 0; i < 8; i++) { s += hv[i]; s2 += hv[i] * hv[i]; }
    #pragma unroll
    for (int o = 16; o; o >>= 1) {
        s  += __shfl_xor_sync(0xffffffffu, s,  o);
        s2 += __shfl_xor_sync(0xffffffffu, s2, o);
    }
    float mean = s * (1.0f / 256.0f);
    float var  = s2 * (1.0f / 256.0f) - mean * mean;
    float rstd = rsqrtf(var + EPS);
    float* hrow = h + (size_t)row * 256;
    float* mrow = m + (size_t)row * 256;
    #pragma unroll
    for (int g = 0; g < 2; g++) {
        int c = g ? c2i : c1;
        float4 gv = *(const float4*)&gg[c];
        float4 bv = *(const float4*)&bb[c];
        float4 hvv = make_float4(hv[g*4+0], hv[g*4+1], hv[g*4+2], hv[g*4+3]);
        float4 mv;
        mv.x = (hvv.x - mean) * rstd * gv.x + bv.x;
        mv.y = (hvv.y - mean) * rstd * gv.y + bv.y;
        mv.z = (hvv.z - mean) * rstd * gv.z + bv.z;
        mv.w = (hvv.w - mean) * rstd * gv.w + bv.w;
        *(float4*)&hrow[c] = hvv;
        *(float4*)&mrow[c] = mv;
    }
}

// ---------------- host side ------------------------------------------------
extern "C" void kernel_launch(void* const* d_in, const int* in_sizes, int n_in,
                              void* d_out, int out_size) {
    const float* inputs     = (const float*)d_in[0];
    const float* init_noise = (const float*)d_in[1];
    const float* slots_mu   = (const float*)d_in[2];
    const float* slots_sig  = (const float*)d_in[3];
    const float* ln_in_g    = (const float*)d_in[4];
    const float* ln_in_b    = (const float*)d_in[5];
    const float* ln_s_g     = (const float*)d_in[6];
    const float* ln_s_b     = (const float*)d_in[7];
    const float* ln_m_g     = (const float*)d_in[8];
    const float* ln_m_b     = (const float*)d_in[9];
    const float* Wk         = (const float*)d_in[10];
    const float* bk         = (const float*)d_in[11];
    const float* Wv         = (const float*)d_in[12];
    const float* bv         = (const float*)d_in[13];
    const float* Wq         = (const float*)d_in[14];
    const float* bq         = (const float*)d_in[15];
    const float* W_ih       = (const float*)d_in[16];
    const float* W_hh       = (const float*)d_in[17];
    const float* b_ih       = (const float*)d_in[18];
    const float* b_hh       = (const float*)d_in[19];
    const float* W1         = (const float*)d_in[20];
    const float* b1         = (const float*)d_in[21];
    const float* W2         = (const float*)d_in[22];
    const float* b2         = (const float*)d_in[23];
    float* out = (float*)d_out;

    float *slots, *qkp, *ct, *uv, *r, *part, *rpart;
    float *gi, *gh, *h, *m, *t, *Wqk, *Wiv, *us, *bqk, *biv, *c0, *prec;
    cudaGetSymbolAddress((void**)&slots, g_slots);
    cudaGetSymbolAddress((void**)&qkp,   g_qkp);
    cudaGetSymbolAddress((void**)&ct,    g_ct);
    cudaGetSymbolAddress((void**)&uv,    g_uv);
    cudaGetSymbolAddress((void**)&r,     g_r);
    cudaGetSymbolAddress((void**)&part,  g_part);
    cudaGetSymbolAddress((void**)&rpart, g_rpart);
    cudaGetSymbolAddress((void**)&gi,    g_gi);
    cudaGetSymbolAddress((void**)&gh,    g_gh);
    cudaGetSymbolAddress((void**)&h,     g_h);
    cudaGetSymbolAddress((void**)&m,     g_m);
    cudaGetSymbolAddress((void**)&t,     g_t);
    cudaGetSymbolAddress((void**)&Wqk,   g_Wqk);
    cudaGetSymbolAddress((void**)&Wiv,   g_Wiv);
    cudaGetSymbolAddress((void**)&us,    g_us);
    cudaGetSymbolAddress((void**)&bqk,   g_bqk);
    cudaGetSymbolAddress((void**)&biv,   g_biv);
    cudaGetSymbolAddress((void**)&c0,    g_c0);
    cudaGetSymbolAddress((void**)&prec,  g_prec);

    cudaFuncSetAttribute(fused_attn_kernel,
                         cudaFuncAttributeMaxDynamicSharedMemorySize, FUSED_SMEM);
    cudaFuncSetAttribute(front_kernel,
                         cudaFuncAttributeMaxDynamicSharedMemorySize, FRONT_SMEM);

    const int BSD = ROWS * D_;      // 131072
    const int BSN = B_ * S_ * N_;   // 2097152

    // prologue
    slots_init_kernel<<<BSD / 256, 256>>>(init_noise, slots_mu, slots_sig, slots);
    prec_kernel<<<dim3(162, 4), 256>>>(Wk, Wq, W_ih, Wv, bk, bq, bv,
                                       prec, us, bqk, c0, biv);
    prec_reduce_kernel<<<256, 256>>>(prec, Wqk, Wiv);

    float* attn_out = out + (out_size - BSN);

    for (int it = 0; it < 3; it++) {
        front_kernel<<<dim3(DIN / 64, ROWS / 64, 4), 256, FRONT_SMEM>>>(
            slots, ln_s_g, ln_s_b, Wqk, us, c0, qkp, ct);
        fused_attn_kernel<<<dim3(NGRP, B_), 256, FUSED_SMEM>>>(
            inputs, ln_in_g, ln_in_b, qkp, bqk, ct, part, rpart,
            (it == 2) ? attn_out : nullptr);
        reduce_kernel<<<(ROWS * DIN) / 1024, 256>>>(part, rpart, uv, r);
        gigh_kernel<<<dim3((3 * D_) / 64, ROWS / 64, 2), 256>>>(
            uv, slots, Wiv, W_hh, b_ih, b_hh, r, biv, gi, gh);
        gru_ln_kernel<<<ROWS / 8, 256>>>(gi, gh, slots, ln_m_g, ln_m_b, h, m);
        mlp1_kernel<<<dim3(H_ / 64, ROWS / 64), 256>>>(m, W1, b1, t);
        mlp2_kernel<<<dim3(D_ / 64, ROWS / 64), 256>>>(
            t, W2, b2, h, (it == 2) ? out : slots);
    }
}

// round 15
// speedup vs baseline: 1.1893x; 1.0699x over previous
#include <cuda_runtime.h>
#include <cstddef>
#include <cstdint>

#define B_  32
#define N_  4096
#define DIN 256
#define D_  256
#define S_  16
#define H_  512
#define EPS 1e-5f
#define SCALE 0.0625f
#define NB 64
#define GRP 8                // tiles per fused block
#define NGRP 8               // groups per batch
#define XS 260               // xsm row stride (floats)
#define AS 20                // atsm row stride
#define ROWS (B_*S_)         // 512

typedef unsigned long long u64;

__device__ __forceinline__ u64 fma2(u64 a, u64 b, u64 c) {
    u64 d;
    asm("fma.rn.f32x2 %0, %1, %2, %3;" : "=l"(d) : "l"(a), "l"(b), "l"(c));
    return d;
}
__device__ __forceinline__ u64 pack2(float lo, float hi) {
    u64 d;
    asm("mov.b64 %0, {%1, %2};" : "=l"(d) : "f"(lo), "f"(hi));
    return d;
}
__device__ __forceinline__ void unpack2(u64 v, float& lo, float& hi) {
    asm("mov.b64 {%0, %1}, %2;" : "=f"(lo), "=f"(hi) : "l"(v));
}
__device__ __forceinline__ float hsum2(u64 v) {
    float a, b; unpack2(v, a, b); return a + b;
}
__device__ __forceinline__ float sigmoidf(float x) { return 1.0f / (1.0f + __expf(-x)); }

// ---------------- scratch ----------------
__device__ float g_slots[ROWS * D_];
__device__ float g_qkp  [4 * ROWS * DIN];
__device__ float g_ct   [ROWS];
__device__ float g_uv   [ROWS * DIN];
__device__ float g_r    [ROWS];
__device__ float g_part [(size_t)B_ * NGRP * S_ * DIN];
__device__ float g_rpart[B_ * NGRP * S_];
__device__ float g_gi   [ROWS * 3 * D_];
__device__ float g_gh   [ROWS * 3 * D_];
__device__ float g_h    [ROWS * D_];
__device__ float g_m    [ROWS * D_];
__device__ float g_t    [ROWS * H_];
__device__ float g_Wqk  [DIN * D_];
__device__ float g_Wiv  [3 * D_ * DIN];
__device__ float g_us   [D_];
__device__ float g_bqk  [DIN];
__device__ float g_biv  [3 * D_];
__device__ float g_c0   [1];
__device__ float g_prec [4 * 64 * 4096];

// ---------------- slots init ----------------
__global__ void slots_init_kernel(const float* __restrict__ noise,
                                  const float* __restrict__ mu,
                                  const float* __restrict__ sigma,
                                  float* __restrict__ slots) {
    int i = blockIdx.x * 256 + threadIdx.x;
    int d = i & (D_ - 1);
    slots[i] = mu[d] + sigma[d] * noise[i];
}

// ------------- combined split-k precompute + prep -------------------------
__global__ __launch_bounds__(256) void prec_kernel(
    const float* __restrict__ Wk, const float* __restrict__ Wq,
    const float* __restrict__ Wih, const float* __restrict__ Wv,
    const float* __restrict__ bk, const float* __restrict__ bq,
    const float* __restrict__ bv,
    float* __restrict__ partial,
    float* __restrict__ us, float* __restrict__ bqk,
    float* __restrict__ c0, float* __restrict__ biv) {
    int t = threadIdx.x;
    int tile = blockIdx.x, ks = blockIdx.y;

    if (tile >= 64) {
        if (ks != 0) return;
        int bx = tile - 64;
        if (bx < 96) {
            int warp = t >> 5, lane = t & 31;
            int r = bx * 8 + warp;
            float s = 0.0f;
            #pragma unroll
            for (int e = lane; e < D_; e += 32) s += Wih[(size_t)r * D_ + e] * bv[e];
            #pragma unroll
            for (int o = 16; o; o >>= 1) s += __shfl_xor_sync(0xffffffffu, s, o);
            if (lane == 0) biv[r] = s;
        } else if (bx == 96) {
            float s = 0.0f;
            for (int e = 0; e < D_; e++) s += bk[e] * Wq[(size_t)e * D_ + t];
            us[t] = SCALE * s;
            if (t == 0) {
                float c = 0.0f;
                for (int e = 0; e < D_; e++) c += bk[e] * bq[e];
                *c0 = SCALE * c;
            }
        } else {
            float s = 0.0f;
            for (int e = 0; e < D_; e++) s += bq[e] * Wk[(size_t)e * DIN + t];
            bqk[t] = SCALE * s;
        }
        return;
    }

    __shared__ float As[16][68];
    __shared__ float Bs[16][68];
    bool ta = (tile < 16);
    int t2 = ta ? tile : tile - 16;
    int m0 = (t2 >> 2) * 64, n0 = (t2 & 3) * 64;
    const float* A  = ta ? Wk : Wih;
    const float* Bm = ta ? Wq : Wv;
    int kbase = ks * 64;
    int tx = t & 15, ty = t >> 4;
    int mB = t & 63, kkb = t >> 6;
    int lm = t >> 2, lk = (t & 3) * 4;

    u64 c2[4][2];
    #pragma unroll
    for (int i = 0; i < 4; i++) { c2[i][0] = 0ull; c2[i][1] = 0ull; }

    float ar[4], br[4];
    float4 av;
    if (ta) {
        #pragma unroll
        for (int i = 0; i < 4; i++)
            ar[i] = A[(size_t)(kbase + kkb + 4 * i) * 256 + m0 + mB];
    } else {
        av = *(const float4*)&A[(size_t)(m0 + lm) * 256 + kbase + lk];
    }
    #pragma unroll
    for (int i = 0; i < 4; i++)
        br[i] = Bm[(size_t)(kbase + kkb + 4 * i) * 256 + n0 + mB];

    for (int ki = 0; ki < 4; ki++) {
        if (ta) {
            #pragma unroll
            for (int i = 0; i < 4; i++) As[kkb + 4 * i][mB] = ar[i];
        } else {
            As[lk + 0][lm] = av.x; As[lk + 1][lm] = av.y;
            As[lk + 2][lm] = av.z; As[lk + 3][lm] = av.w;
        }
        #pragma unroll
        for (int i = 0; i < 4; i++) Bs[kkb + 4 * i][mB] = br[i];
        __syncthreads();
        if (ki < 3) {
            int knext = kbase + (ki + 1) * 16;
            if (ta) {
                #pragma unroll
                for (int i = 0; i < 4; i++)
                    ar[i] = A[(size_t)(knext + kkb + 4 * i) * 256 + m0 + mB];
            } else {
                av = *(const float4*)&A[(size_t)(m0 + lm) * 256 + knext + lk];
            }
            #pragma unroll
            for (int i = 0; i < 4; i++)
                br[i] = Bm[(size_t)(knext + kkb + 4 * i) * 256 + n0 + mB];
        }
        #pragma unroll
        for (int kk = 0; kk < 16; kk++) {
            ulonglong2 w2 = *(const ulonglong2*)&Bs[kk][tx * 4];
            #pragma unroll
            for (int i = 0; i < 4; i++) {
                float ai = As[kk][ty * 4 + i];
                u64 a2 = pack2(ai, ai);
                c2[i][0] = fma2(a2, w2.x, c2[i][0]);
                c2[i][1] = fma2(a2, w2.y, c2[i][1]);
            }
        }
        __syncthreads();
    }

    size_t base = ((size_t)(ks * 64 + tile)) * 4096;
    #pragma unroll
    for (int i = 0; i < 4; i++) {
        #pragma unroll
        for (int p = 0; p < 2; p++) {
            float v0, v1;
            unpack2(c2[i][p], v0, v1);
            int off = (ty * 4 + i) * 64 + tx * 4 + 2 * p;
            partial[base + off]     = v0;
            partial[base + off + 1] = v1;
        }
    }
}

__global__ void prec_reduce_kernel(const float* __restrict__ partial,
                                   float* __restrict__ Wqk,
                                   float* __restrict__ Wiv) {
    int idx4 = blockIdx.x * 256 + threadIdx.x;
    int tile = idx4 >> 10;
    int w4 = (idx4 & 1023) * 4;
    const float* p = partial + (size_t)tile * 4096 + w4;
    float4 s = *(const float4*)p;
    #pragma unroll
    for (int ks = 1; ks < 4; ks++) {
        float4 v = *(const float4*)(p + (size_t)ks * 64 * 4096);
        s.x += v.x; s.y += v.y; s.z += v.z; s.w += v.w;
    }
    int i = w4 >> 6, j = w4 & 63;
    if (tile < 16) {
        int m = (tile >> 2) * 64 + i, n = (tile & 3) * 64 + j;
        s.x *= SCALE; s.y *= SCALE; s.z *= SCALE; s.w *= SCALE;
        *(float4*)&Wqk[(size_t)m * 256 + n] = s;
    } else {
        int t2 = tile - 16;
        int m = (t2 >> 2) * 64 + i, n = (t2 & 3) * 64 + j;
        *(float4*)&Wiv[(size_t)m * 256 + n] = s;
    }
}

// ---- shared gemm body (explicit tile origin) -----------------------------
__device__ __forceinline__ void gemm_body(
    const float* __restrict__ A, const float* __restrict__ W,
    const float* __restrict__ bias, const float* __restrict__ extraM,
    const float* __restrict__ rvec, const float* __restrict__ cvec,
    float* __restrict__ C, int Nn, int K, int mode, int m0, int n0,
    float* As, float* Ws) {
    int t = threadIdx.x, tx = t & 15, ty = t >> 4;
    int lm = t >> 2, lk = (t & 3) * 4;
    u64 c2[4][2];
    #pragma unroll
    for (int i = 0; i < 4; i++) { c2[i][0] = 0ull; c2[i][1] = 0ull; }

    float4 av = *(const float4*)&A[(size_t)(m0 + lm) * K + lk];
    float4 wv = *(const float4*)&W[(size_t)(n0 + lm) * K + lk];

    for (int k0 = 0; k0 < K; k0 += 16) {
        As[(lk + 0) * 68 + lm] = av.x; As[(lk + 1) * 68 + lm] = av.y;
        As[(lk + 2) * 68 + lm] = av.z; As[(lk + 3) * 68 + lm] = av.w;
        Ws[(lk + 0) * 68 + lm] = wv.x; Ws[(lk + 1) * 68 + lm] = wv.y;
        Ws[(lk + 2) * 68 + lm] = wv.z; Ws[(lk + 3) * 68 + lm] = wv.w;
        __syncthreads();
        if (k0 + 16 < K) {
            av = *(const float4*)&A[(size_t)(m0 + lm) * K + k0 + 16 + lk];
            wv = *(const float4*)&W[(size_t)(n0 + lm) * K + k0 + 16 + lk];
        }
        #pragma unroll
        for (int kk = 0; kk < 16; kk++) {
            float4 a = *(const float4*)&As[kk * 68 + ty * 4];
            ulonglong2 w2 = *(const ulonglong2*)&Ws[kk * 68 + tx * 4];
            float arr[4] = {a.x, a.y, a.z, a.w};
            #pragma unroll
            for (int i = 0; i < 4; i++) {
                u64 a2 = pack2(arr[i], arr[i]);
                c2[i][0] = fma2(a2, w2.x, c2[i][0]);
                c2[i][1] = fma2(a2, w2.y, c2[i][1]);
            }
        }
        __syncthreads();
    }
    #pragma unroll
    for (int i = 0; i < 4; i++) {
        int r = m0 + ty * 4 + i;
        #pragma unroll
        for (int p = 0; p < 2; p++) {
            float v0, v1;
            unpack2(c2[i][p], v0, v1);
            int c0c = n0 + tx * 4 + 2 * p;
            v0 += bias[c0c]; v1 += bias[c0c + 1];
            if (mode == 1) { v0 = fmaxf(v0, 0.0f); v1 = fmaxf(v1, 0.0f); }
            if (mode == 2) {
                v0 += extraM[(size_t)r * Nn + c0c];
                v1 += extraM[(size_t)r * Nn + c0c + 1];
            }
            if (mode == 3) {
                float rv = rvec[r];
                v0 += rv * cvec[c0c]; v1 += rv * cvec[c0c + 1];
            }
            C[(size_t)r * Nn + c0c]     = v0;
            C[(size_t)r * Nn + c0c + 1] = v1;
        }
    }
}

__global__ __launch_bounds__(256) void gi_kernel(
    const float* __restrict__ uv, const float* __restrict__ Wiv,
    const float* __restrict__ bih,
    const float* __restrict__ r, const float* __restrict__ biv,
    float* __restrict__ gi) {
    __shared__ float As[16 * 68];
    __shared__ float Ws[16 * 68];
    gemm_body(uv, Wiv, bih, nullptr, r, biv, gi, 3 * D_, DIN, 3,
              blockIdx.y * 64, blockIdx.x * 64, As, Ws);
}

__global__ __launch_bounds__(256) void mlp1_kernel(
    const float* __restrict__ m, const float* __restrict__ W1,
    const float* __restrict__ b1, float* __restrict__ t) {
    __shared__ float As[16 * 68];
    __shared__ float Ws[16 * 68];
    gemm_body(m, W1, b1, nullptr, nullptr, nullptr, t, H_, D_, 1,
              blockIdx.y * 64, blockIdx.x * 64, As, Ws);
}

__global__ __launch_bounds__(256) void mlp2_kernel(
    const float* __restrict__ t, const float* __restrict__ W2,
    const float* __restrict__ b2, const float* __restrict__ h,
    float* __restrict__ outp) {
    __shared__ float As[16 * 68];
    __shared__ float Ws[16 * 68];
    gemm_body(t, W2, b2, h, nullptr, nullptr, outp, D_, H_, 2,
              blockIdx.y * 64, blockIdx.x * 64, As, Ws);
}

// ------- front2: [0,128) LN(slots)+split-k qk+ct ; [128,224) gh gemm ------
#define FRONT_SMEM ((64 * XS + 16 * 68) * 4)
__global__ __launch_bounds__(256) void front2_kernel(
    const float* __restrict__ slots,
    const float* __restrict__ ln_g, const float* __restrict__ ln_b,
    const float* __restrict__ Wqk,
    const float* __restrict__ us, const float* __restrict__ c0,
    float* __restrict__ qkp, float* __restrict__ ct,
    const float* __restrict__ Whh, const float* __restrict__ bhh,
    float* __restrict__ gh) {
    extern __shared__ float sm[];
    int bxx = blockIdx.x;
    if (bxx >= 128) {                       // ---- gh gemm tiles ----
        int g = bxx - 128;                  // 0..95 -> 12 x-tiles, 8 y-tiles
        gemm_body(slots, Whh, bhh, nullptr, nullptr, nullptr, gh,
                  3 * D_, D_, 0, (g / 12) * 64, (g % 12) * 64,
                  sm, sm + 16 * 68);
        return;
    }
    float* snS = sm;
    float* Ws  = sm + 64 * XS;
    int t = threadIdx.x, w = t >> 5, lane = t & 31;
    int r0 = ((bxx >> 2) & 7) * 64, c0b = (bxx & 3) * 64;
    int ks = bxx >> 5, kbase = ks * 64;

    const float4* g4 = (const float4*)ln_g;
    const float4* b4 = (const float4*)ln_b;
    float4 ga = g4[lane], gc = g4[lane + 32];
    float4 ba = b4[lane], bc = b4[lane + 32];

    #pragma unroll
    for (int bt = 0; bt < 2; bt++) {
        float4 ar[4], cr[4];
        #pragma unroll
        for (int rr = 0; rr < 4; rr++) {
            int lr = w * 8 + bt * 4 + rr;
            const float4* x4 = (const float4*)(slots + (size_t)(r0 + lr) * 256);
            ar[rr] = x4[lane];
            cr[rr] = x4[lane + 32];
        }
        #pragma unroll
        for (int rr = 0; rr < 4; rr++) {
            int lr = w * 8 + bt * 4 + rr;
            float4 a = ar[rr], c = cr[rr];
            float s  = a.x + a.y + a.z + a.w + c.x + c.y + c.z + c.w;
            float s2 = a.x*a.x + a.y*a.y + a.z*a.z + a.w*a.w
                     + c.x*c.x + c.y*c.y + c.z*c.z + c.w*c.w;
            #pragma unroll
            for (int o = 16; o; o >>= 1) {
                s  += __shfl_xor_sync(0xffffffffu, s,  o);
                s2 += __shfl_xor_sync(0xffffffffu, s2, o);
            }
            float mean = s * (1.0f / 256.0f);
            float var  = s2 * (1.0f / 256.0f) - mean * mean;
            float rstd = rsqrtf(var + EPS);
            float4 o1, o2;
            o1.x = (a.x - mean) * rstd * ga.x + ba.x;
            o1.y = (a.y - mean) * rstd * ga.y + ba.y;
            o1.z = (a.z - mean) * rstd * ga.z + ba.z;
            o1.w = (a.w - mean) * rstd * ga.w + ba.w;
            o2.x = (c.x - mean) * rstd * gc.x + bc.x;
            o2.y = (c.y - mean) * rstd * gc.y + bc.y;
            o2.z = (c.z - mean) * rstd * gc.z + bc.z;
            o2.w = (c.w - mean) * rstd * gc.w + bc.w;
            *(float4*)&snS[lr * XS + lane * 4] = o1;
            *(float4*)&snS[lr * XS + (lane + 32) * 4] = o2;
        }
    }
    __syncthreads();

    if (c0b == 0 && ks == 0 && t < 64) {
        float s = 0.0f;
        #pragma unroll 8
        for (int e = 0; e < 256; e++) s += snS[t * XS + e] * us[e];
        ct[r0 + t] = s + c0[0];
    }
    __syncthreads();

    int tx = t & 15, ty = t >> 4, lm = t >> 2, lk = (t & 3) * 4;
    u64 c2[4][2];
    #pragma unroll
    for (int i = 0; i < 4; i++) { c2[i][0] = 0ull; c2[i][1] = 0ull; }
    float4 wv = *(const float4*)&Wqk[(size_t)(c0b + lm) * 256 + kbase + lk];
    #pragma unroll
    for (int kc = 0; kc < 4; kc++) {
        int k0 = kbase + kc * 16;
        Ws[(lk + 0) * 68 + lm] = wv.x; Ws[(lk + 1) * 68 + lm] = wv.y;
        Ws[(lk + 2) * 68 + lm] = wv.z; Ws[(lk + 3) * 68 + lm] = wv.w;
        __syncthreads();
        if (kc < 3)
            wv = *(const float4*)&Wqk[(size_t)(c0b + lm) * 256 + k0 + 16 + lk];
        #pragma unroll
        for (int kk = 0; kk < 16; kk++) {
            ulonglong2 w2 = *(const ulonglong2*)&Ws[kk * 68 + tx * 4];
            #pragma unroll
            for (int i = 0; i < 4; i++) {
                float ai = snS[(ty * 4 + i) * XS + k0 + kk];
                u64 a2 = pack2(ai, ai);
                c2[i][0] = fma2(a2, w2.x, c2[i][0]);
                c2[i][1] = fma2(a2, w2.y, c2[i][1]);
            }
        }
        __syncthreads();
    }
    float* qo = qkp + (size_t)ks * ROWS * 256;
    #pragma unroll
    for (int i = 0; i < 4; i++) {
        int r = r0 + ty * 4 + i;
        #pragma unroll
        for (int p = 0; p < 2; p++) {
            float v0, v1;
            unpack2(c2[i][p], v0, v1);
            int cc = c0b + tx * 4 + 2 * p;
            qo[(size_t)r * 256 + cc]     = v0;
            qo[(size_t)r * 256 + cc + 1] = v1;
        }
    }
}

// --------- fused: LDG->LN->smem, logits, softmax, attn@x ------------------
#define FUSED_SMEM ((64 * XS + 16 * 256 + 1024 + 1024 + 64 * AS + 16 + 32) * 4)

__global__ __launch_bounds__(256, 2) void fused_attn_kernel(
    const float* __restrict__ X,
    const float* __restrict__ lng, const float* __restrict__ lnb,
    const float* __restrict__ QKP, const float* __restrict__ bqk,
    const float* __restrict__ CT,
    float* __restrict__ part, float* __restrict__ rpart,
    float* __restrict__ attn_out) {
    extern __shared__ float sm[];
    float* xsm  = sm;                       // [64][XS]
    float* qsm  = sm + 64 * XS;             // [16][256]
    float* redA = qsm + 16 * 256;           // [16][64]
    float* redB = redA + 1024;              // [16][64]
    float* atsm = redB + 1024;              // [64][AS]
    float* csm  = atsm + 64 * AS;           // [16]
    float* wred = csm + 16;                 // [2][16]
    int b = blockIdx.y, grp = blockIdx.x;
    int tid = threadIdx.x;
    int w = tid >> 5, lane = tid & 31;

    const float4* g4 = (const float4*)lng;
    const float4* b4 = (const float4*)lnb;
    float4 ga = g4[lane], gc = g4[lane + 32];
    float4 ba = b4[lane], bc = b4[lane + 32];

    // per-block loads: qsm = sum of 4 qk partials + bqk; ct
    for (int e = tid; e < S_ * 64; e += 256) {
        int s = e >> 6, c4 = (e & 63) * 4;
        size_t off = ((size_t)b * S_ + s) * 256 + c4;
        float4 q0 = *(const float4*)&QKP[off];
        float4 q1 = *(const float4*)&QKP[(size_t)ROWS * 256 + off];
        float4 q2 = *(const float4*)&QKP[(size_t)2 * ROWS * 256 + off];
        float4 q3 = *(const float4*)&QKP[(size_t)3 * ROWS * 256 + off];
        float4 bb4 = *(const float4*)&bqk[c4];
        float4 qv;
        qv.x = q0.x + q1.x + q2.x + q3.x + bb4.x;
        qv.y = q0.y + q1.y + q2.y + q3.y + bb4.y;
        qv.z = q0.z + q1.z + q2.z + q3.z + bb4.z;
        qv.w = q0.w + q1.w + q2.w + q3.w + bb4.w;
        *(float4*)&qsm[s * 256 + c4] = qv;
    }
    if (tid < S_) csm[tid] = CT[b * S_ + tid];

    int n = tid & 63, dq = tid >> 6;
    int db = dq * 64;
    u64 uacc[8];
    #pragma unroll
    for (int sp = 0; sp < 8; sp++) uacc[sp] = 0ull;
    float rtot = 0.0f;

    for (int tl = 0; tl < GRP; tl++) {
        int tile = grp * GRP + tl;
        int n0 = tile * NB;
        const float* xb = X + ((size_t)b * N_ + n0) * DIN;
        __syncthreads();   // covers q/ct on tl==0; xsm/atsm reuse after

        // ---- load + LN fused: warp w owns rows 8w..8w+7, batched prefetch ----
        #pragma unroll
        for (int bt = 0; bt < 2; bt++) {
            float4 ar[4], cr[4];
            #pragma unroll
            for (int rr = 0; rr < 4; rr++) {
                int lr = w * 8 + bt * 4 + rr;
                const float4* x4 = (const float4*)(xb + (size_t)lr * DIN);
                ar[rr] = x4[lane];
                cr[rr] = x4[lane + 32];
            }
            #pragma unroll
            for (int rr = 0; rr < 4; rr++) {
                int lr = w * 8 + bt * 4 + rr;
                float4 a = ar[rr], c = cr[rr];
                float s  = a.x + a.y + a.z + a.w + c.x + c.y + c.z + c.w;
                float s2 = a.x*a.x + a.y*a.y + a.z*a.z + a.w*a.w
                         + c.x*c.x + c.y*c.y + c.z*c.z + c.w*c.w;
                #pragma unroll
                for (int o = 16; o; o >>= 1) {
                    s  += __shfl_xor_sync(0xffffffffu, s,  o);
                    s2 += __shfl_xor_sync(0xffffffffu, s2, o);
                }
                float mean = s * (1.0f / 256.0f);
                float var  = s2 * (1.0f / 256.0f) - mean * mean;
                float rstd = rsqrtf(var + EPS);
                float4 o1, o2;
                o1.x = (a.x - mean) * rstd * ga.x + ba.x;
                o1.y = (a.y - mean) * rstd * ga.y + ba.y;
                o1.z = (a.z - mean) * rstd * ga.z + ba.z;
                o1.w = (a.w - mean) * rstd * ga.w + ba.w;
                o2.x = (c.x - mean) * rstd * gc.x + bc.x;
                o2.y = (c.y - mean) * rstd * gc.y + bc.y;
                o2.z = (c.z - mean) * rstd * gc.z + bc.z;
                o2.w = (c.w - mean) * rstd * gc.w + bc.w;
                *(float4*)&xsm[lr * XS + lane * 4] = o1;
                *(float4*)&xsm[lr * XS + (lane + 32) * 4] = o2;
            }
        }
        __syncthreads();

        // ---- phase 1: logits[n][s] ----
        u64 acc[S_];
        #pragma unroll
        for (int s = 0; s < S_; s++) acc[s] = 0ull;
        const ulonglong2* xr = (const ulonglong2*)(xsm + n * XS + db);
        #pragma unroll 4
        for (int i = 0; i < 16; i++) {
            ulonglong2 xv = xr[i];
            const float* qb = qsm + db + i * 4;
            #pragma unroll
            for (int s = 0; s < S_; s++) {
                ulonglong2 qv = *(const ulonglong2*)(qb + s * 256);
                acc[s] = fma2(xv.x, qv.x, acc[s]);
                acc[s] = fma2(xv.y, qv.y, acc[s]);
            }
        }
        float p[S_];
        #pragma unroll
        for (int s = 0; s < S_; s++) p[s] = hsum2(acc[s]);

        if (dq == 2) {
            #pragma unroll
            for (int s = 0; s < S_; s++) redA[s * 64 + n] = p[s];
        }
        if (dq == 3) {
            #pragma unroll
            for (int s = 0; s < S_; s++) redB[s * 64 + n] = p[s];
        }
        __syncthreads();
        if (dq == 0) {
            #pragma unroll
            for (int s = 0; s < S_; s++) p[s] += redA[s * 64 + n];
        }
        if (dq == 1) {
            #pragma unroll
            for (int s = 0; s < S_; s++) {
                p[s] += redB[s * 64 + n];
                redB[s * 64 + n] = p[s];
            }
        }
        __syncthreads();

        // ---- softmax over s + rowsum ----
        if (tid < 64) {
            float mx = -1e30f;
            #pragma unroll
            for (int s = 0; s < S_; s++) {
                p[s] = p[s] + redB[s * 64 + n] + csm[s];
                mx = fmaxf(mx, p[s]);
            }
            float sum = 0.0f;
            #pragma unroll
            for (int s = 0; s < S_; s++) { p[s] = __expf(p[s] - mx); sum += p[s]; }
            float inv = 1.0f / sum;
            #pragma unroll
            for (int s = 0; s < S_; s++) {
                float a = p[s] * inv;
                p[s] = a;
                atsm[n * AS + s] = a;
                if (attn_out)
                    attn_out[((size_t)(b * S_ + s)) * N_ + n0 + n] = a;
            }
            #pragma unroll
            for (int s = 0; s < S_; s++) {
                float v = p[s];
                #pragma unroll
                for (int o = 16; o; o >>= 1) v += __shfl_xor_sync(0xffffffffu, v, o);
                if ((tid & 31) == 0) wred[(tid >> 5) * 16 + s] = v;
            }
        }
        __syncthreads();
        if (tid < S_) rtot += wred[tid] + wred[16 + tid];

        // ---- phase 3: accumulate uv ----
        #pragma unroll 4
        for (int nn = 0; nn < NB; nn++) {
            float xv = xsm[nn * XS + tid];
            u64 x2 = pack2(xv, xv);
            const ulonglong2* arow2 = (const ulonglong2*)(atsm + nn * AS);
            #pragma unroll
            for (int jj = 0; jj < 4; jj++) {
                ulonglong2 ap = arow2[jj];
                uacc[2 * jj]     = fma2(x2, ap.x, uacc[2 * jj]);
                uacc[2 * jj + 1] = fma2(x2, ap.y, uacc[2 * jj + 1]);
            }
        }
    }

    float* po = part + ((size_t)(b * NGRP + grp) * S_) * DIN + tid;
    #pragma unroll
    for (int sp = 0; sp < 8; sp++) {
        float v0, v1;
        unpack2(uacc[sp], v0, v1);
        po[(size_t)(2 * sp) * DIN]     = v0;
        po[(size_t)(2 * sp + 1) * DIN] = v1;
    }
    if (tid < S_)
        rpart[((size_t)b * NGRP + grp) * S_ + tid] = rtot;
}

// ---------------- merged reductions (float4, 8-way) -----------------------
__global__ void reduce_kernel(const float* __restrict__ part,
                              const float* __restrict__ rpart,
                              float* __restrict__ uv,
                              float* __restrict__ r) {
    int idx4 = blockIdx.x * 256 + threadIdx.x;     // 0..32767
    int b = idx4 >> 10;
    int sd4 = (idx4 & 1023) * 4;
    const float* p = part + (size_t)b * NGRP * 4096 + sd4;
    float4 s = make_float4(0.f, 0.f, 0.f, 0.f);
    #pragma unroll
    for (int t = 0; t < NGRP; t++) {
        float4 v = *(const float4*)(p + (size_t)t * 4096);
        s.x += v.x; s.y += v.y; s.z += v.z; s.w += v.w;
    }
    *(float4*)&uv[(size_t)idx4 * 4] = s;
    if (blockIdx.x == 0) {
        for (int i = threadIdx.x; i < ROWS; i += 256) {
            const float* rp = rpart + (i >> 4) * NGRP * S_ + (i & 15);
            float v = 0.0f;
            #pragma unroll
            for (int t = 0; t < NGRP; t++) v += rp[t * S_];
            r[i] = v;
        }
    }
}

// ---------------- GRU + LN(m) fused (warp per row) ------------------------
__global__ void gru_ln_kernel(const float* __restrict__ gi,
                              const float* __restrict__ gh,
                              const float* __restrict__ slots,
                              const float* __restrict__ gg,
                              const float* __restrict__ bb,
                              float* __restrict__ h,
                              float* __restrict__ m) {
    int w = threadIdx.x >> 5, lane = threadIdx.x & 31;
    int row = blockIdx.x * 8 + w;
    const float* gir = gi + (size_t)row * 768;
    const float* ghr = gh + (size_t)row * 768;
    const float* hp  = slots + (size_t)row * 256;
    int c1 = lane * 4, c2i = c1 + 128;
    float hv[8];
    #pragma unroll
    for (int g = 0; g < 2; g++) {
        int c = g ? c2i : c1;
        float4 ir = *(const float4*)&gir[c];
        float4 hr = *(const float4*)&ghr[c];
        float4 iz = *(const float4*)&gir[c + 256];
        float4 hz = *(const float4*)&ghr[c + 256];
        float4 in = *(const float4*)&gir[c + 512];
        float4 hn = *(const float4*)&ghr[c + 512];
        float4 pv = *(const float4*)&hp[c];
        float rr, zz, nn;
        rr = sigmoidf(ir.x + hr.x); zz = sigmoidf(iz.x + hz.x);
        nn = tanhf(in.x + rr * hn.x); hv[g*4+0] = (1.0f - zz) * nn + zz * pv.x;
        rr = sigmoidf(ir.y + hr.y); zz = sigmoidf(iz.y + hz.y);
        nn = tanhf(in.y + rr * hn.y); hv[g*4+1] = (1.0f - zz) * nn + zz * pv.y;
        rr = sigmoidf(ir.z + hr.z); zz = sigmoidf(iz.z + hz.z);
        nn = tanhf(in.z + rr * hn.z); hv[g*4+2] = (1.0f - zz) * nn + zz * pv.z;
        rr = sigmoidf(ir.w + hr.w); zz = sigmoidf(iz.w + hz.w);
        nn = tanhf(in.w + rr * hn.w); hv[g*4+3] = (1.0f - zz) * nn + zz * pv.w;
    }
    float s = 0.0f, s2 = 0.0f;
    #pragma unroll
    for (int i = 0; i < 8; i++) { s += hv[i]; s2 += hv[i] * hv[i]; }
    #pragma unroll
    for (int o = 16; o; o >>= 1) {
        s  += __shfl_xor_sync(0xffffffffu, s,  o);
        s2 += __shfl_xor_sync(0xffffffffu, s2, o);
    }
    float mean = s * (1.0f / 256.0f);
    float var  = s2 * (1.0f / 256.0f) - mean * mean;
    float rstd = rsqrtf(var + EPS);
    float* hrow = h + (size_t)row * 256;
    float* mrow = m + (size_t)row * 256;
    #pragma unroll
    for (int g = 0; g < 2; g++) {
        int c = g ? c2i : c1;
        float4 gv = *(const float4*)&gg[c];
        float4 bv = *(const float4*)&bb[c];
        float4 hvv = make_float4(hv[g*4+0], hv[g*4+1], hv[g*4+2], hv[g*4+3]);
        float4 mv;
        mv.x = (hvv.x - mean) * rstd * gv.x + bv.x;
        mv.y = (hvv.y - mean) * rstd * gv.y + bv.y;
        mv.z = (hvv.z - mean) * rstd * gv.z + bv.z;
        mv.w = (hvv.w - mean) * rstd * gv.w + bv.w;
        *(float4*)&hrow[c] = hvv;
        *(float4*)&mrow[c] = mv;
    }
}

// ---------------- host side ------------------------------------------------
extern "C" void kernel_launch(void* const* d_in, const int* in_sizes, int n_in,
                              void* d_out, int out_size) {
    const float* inputs     = (const float*)d_in[0];
    const float* init_noise = (const float*)d_in[1];
    const float* slots_mu   = (const float*)d_in[2];
    const float* slots_sig  = (const float*)d_in[3];
    const float* ln_in_g    = (const float*)d_in[4];
    const float* ln_in_b    = (const float*)d_in[5];
    const float* ln_s_g     = (const float*)d_in[6];
    const float* ln_s_b     = (const float*)d_in[7];
    const float* ln_m_g     = (const float*)d_in[8];
    const float* ln_m_b     = (const float*)d_in[9];
    const float* Wk         = (const float*)d_in[10];
    const float* bk         = (const float*)d_in[11];
    const float* Wv         = (const float*)d_in[12];
    const float* bv         = (const float*)d_in[13];
    const float* Wq         = (const float*)d_in[14];
    const float* bq         = (const float*)d_in[15];
    const float* W_ih       = (const float*)d_in[16];
    const float* W_hh       = (const float*)d_in[17];
    const float* b_ih       = (const float*)d_in[18];
    const float* b_hh       = (const float*)d_in[19];
    const float* W1         = (const float*)d_in[20];
    const float* b1         = (const float*)d_in[21];
    const float* W2         = (const float*)d_in[22];
    const float* b2         = (const float*)d_in[23];
    float* out = (float*)d_out;

    float *slots, *qkp, *ct, *uv, *r, *part, *rpart;
    float *gi, *gh, *h, *m, *t, *Wqk, *Wiv, *us, *bqk, *biv, *c0, *prec;
    cudaGetSymbolAddress((void**)&slots, g_slots);
    cudaGetSymbolAddress((void**)&qkp,   g_qkp);
    cudaGetSymbolAddress((void**)&ct,    g_ct);
    cudaGetSymbolAddress((void**)&uv,    g_uv);
    cudaGetSymbolAddress((void**)&r,     g_r);
    cudaGetSymbolAddress((void**)&part,  g_part);
    cudaGetSymbolAddress((void**)&rpart, g_rpart);
    cudaGetSymbolAddress((void**)&gi,    g_gi);
    cudaGetSymbolAddress((void**)&gh,    g_gh);
    cudaGetSymbolAddress((void**)&h,     g_h);
    cudaGetSymbolAddress((void**)&m,     g_m);
    cudaGetSymbolAddress((void**)&t,     g_t);
    cudaGetSymbolAddress((void**)&Wqk,   g_Wqk);
    cudaGetSymbolAddress((void**)&Wiv,   g_Wiv);
    cudaGetSymbolAddress((void**)&us,    g_us);
    cudaGetSymbolAddress((void**)&bqk,   g_bqk);
    cudaGetSymbolAddress((void**)&biv,   g_biv);
    cudaGetSymbolAddress((void**)&c0,    g_c0);
    cudaGetSymbolAddress((void**)&prec,  g_prec);

    cudaFuncSetAttribute(fused_attn_kernel,
                         cudaFuncAttributeMaxDynamicSharedMemorySize, FUSED_SMEM);
    cudaFuncSetAttribute(front2_kernel,
                         cudaFuncAttributeMaxDynamicSharedMemorySize, FRONT_SMEM);

    const int BSD = ROWS * D_;      // 131072
    const int BSN = B_ * S_ * N_;   // 2097152

    // prologue
    slots_init_kernel<<<BSD / 256, 256>>>(init_noise, slots_mu, slots_sig, slots);
    prec_kernel<<<dim3(162, 4), 256>>>(Wk, Wq, W_ih, Wv, bk, bq, bv,
                                       prec, us, bqk, c0, biv);
    prec_reduce_kernel<<<256, 256>>>(prec, Wqk, Wiv);

    float* attn_out = out + (out_size - BSN);

    for (int it = 0; it < 3; it++) {
        front2_kernel<<<224, 256, FRONT_SMEM>>>(
            slots, ln_s_g, ln_s_b, Wqk, us, c0, qkp, ct, W_hh, b_hh, gh);
        fused_attn_kernel<<<dim3(NGRP, B_), 256, FUSED_SMEM>>>(
            inputs, ln_in_g, ln_in_b, qkp, bqk, ct, part, rpart,
            (it == 2) ? attn_out : nullptr);
        reduce_kernel<<<(ROWS * DIN) / 1024, 256>>>(part, rpart, uv, r);
        gi_kernel<<<dim3((3 * D_) / 64, ROWS / 64), 256>>>(
            uv, Wiv, b_ih, r, biv, gi);
        gru_ln_kernel<<<ROWS / 8, 256>>>(gi, gh, slots, ln_m_g, ln_m_b, h, m);
        mlp1_kernel<<<dim3(H_ / 64, ROWS / 64), 256>>>(m, W1, b1, t);
        mlp2_kernel<<<dim3(D_ / 64, ROWS / 64), 256>>>(
            t, W2, b2, h, (it == 2) ? out : slots);
    }
}